// round 12
// baseline (speedup 1.0000x reference)
#include <cuda_runtime.h>
#include <cuda_bf16.h>
#include <math.h>
#include <stddef.h>
#include <stdint.h>

// Problem constants
#define TB 2
#define TT 2048
#define NE 1024
#define NH 16
#define HD 64
#define C3 (3 * NE)   // 3072

// Q scale: 1/sqrt(64) * log2(e)  (softmax runs in exp2 domain)
#define QSCALE 0.18033688011112042f

// Fragment-major bf16 hi/lo planes (mma register layout in gmem).
__device__ uint4 g_xAh [(size_t)256 * 64 * 32];   // x      A-frags
__device__ uint4 g_xAl [(size_t)256 * 64 * 32];
__device__ uint4 g_atAh[(size_t)256 * 64 * 32];   // attn out A-frags (gemm2 input)
__device__ uint4 g_atAl[(size_t)256 * 64 * 32];
__device__ uint2 g_WkBh[(size_t)384 * 64 * 32];   // W_kqv  B-frags
__device__ uint2 g_WkBl[(size_t)384 * 64 * 32];
__device__ uint2 g_WpBh[(size_t)128 * 64 * 32];   // W_proj B-frags
__device__ uint2 g_WpBl[(size_t)128 * 64 * 32];

// Attention planes, per (b,h):
__device__ uint4 g_QAh[(size_t)32 * 128 * 4 * 32];
__device__ uint4 g_QAl[(size_t)32 * 128 * 4 * 32];
__device__ uint2 g_KBh[(size_t)32 * 32 * 8 * 4 * 32];
__device__ uint2 g_KBl[(size_t)32 * 32 * 8 * 4 * 32];
__device__ uint2 g_VBh[(size_t)32 * 32 * 8 * 4 * 32];
__device__ uint2 g_VBl[(size_t)32 * 32 * 8 * 4 * 32];

// ===========================================================================
// PTX helpers
// ===========================================================================
static __device__ __forceinline__ void mma16816(float* d, const uint4& a, const uint2& b) {
    asm volatile(
        "mma.sync.aligned.m16n8k16.row.col.f32.bf16.bf16.f32 "
        "{%0,%1,%2,%3}, {%4,%5,%6,%7}, {%8,%9}, {%0,%1,%2,%3};"
        : "+f"(d[0]), "+f"(d[1]), "+f"(d[2]), "+f"(d[3])
        : "r"(a.x), "r"(a.y), "r"(a.z), "r"(a.w), "r"(b.x), "r"(b.y));
}

static __device__ __forceinline__ void split2(float2 f, uint32_t& h, uint32_t& l) {
    __nv_bfloat162 hp = __floats2bfloat162_rn(f.x, f.y);
    float2 hf = __bfloat1622float2(hp);
    __nv_bfloat162 lp = __floats2bfloat162_rn(f.x - hf.x, f.y - hf.y);
    h = *reinterpret_cast<uint32_t*>(&hp);
    l = *reinterpret_cast<uint32_t*>(&lp);
}

static __device__ __forceinline__ float ex2(float x) {
    float r;
    asm("ex2.approx.f32 %0, %1;" : "=f"(r) : "f"(x));
    return r;
}

static __device__ __forceinline__ uint32_t smem_u32(const void* p) {
    uint32_t a;
    asm("{ .reg .u64 t; cvta.to.shared.u64 t, %1; cvt.u32.u64 %0, t; }"
        : "=r"(a) : "l"(p));
    return a;
}

#define CP16(dst, src) \
    asm volatile("cp.async.cg.shared.global [%0], [%1], 16;" :: "r"(dst), "l"(src))
#define CP_COMMIT() asm volatile("cp.async.commit_group;" ::: "memory")
#define CP_WAIT2()  asm volatile("cp.async.wait_group 2;" ::: "memory")
#define CP_WAIT1()  asm volatile("cp.async.wait_group 1;" ::: "memory")
#define CP_WAIT0()  asm volatile("cp.async.wait_group 0;" ::: "memory")

// ===========================================================================
// Merged prep kernel: one launch converts x (A-frags), W_kqv, W_proj (B-frags)
//   blocks [0,2048)      : x -> g_xA*
//   blocks [2048,5120)   : W_kqv -> g_WkB*
//   blocks [5120,6144)   : W_proj -> g_WpB*
// ===========================================================================
__global__ __launch_bounds__(256)
void prep_all(const float* __restrict__ x, const float* __restrict__ Wk,
              const float* __restrict__ Wp)
{
    int blk = blockIdx.x;
    if (blk < 2048) {
        int slot = blk * 256 + threadIdx.x;
        int frag = slot >> 5, la = slot & 31;
        int row = ((frag >> 6) << 4) + (la >> 2);
        int k   = ((frag & 63) << 4) + ((la & 3) << 1);
        const float* p = x + (size_t)row * 1024 + k;
        float2 x0 = *(const float2*)p;
        float2 x1 = *(const float2*)(p + 8 * 1024);
        float2 x2 = *(const float2*)(p + 8);
        float2 x3 = *(const float2*)(p + 8 * 1024 + 8);
        uint4 h, l;
        split2(x0, h.x, l.x);
        split2(x1, h.y, l.y);
        split2(x2, h.z, l.z);
        split2(x3, h.w, l.w);
        g_xAh[slot] = h;
        g_xAl[slot] = l;
    } else {
        const float* src;
        uint2 *hi, *lo;
        int slot;
        if (blk < 5120) {
            slot = (blk - 2048) * 256 + threadIdx.x;
            src = Wk; hi = g_WkBh; lo = g_WkBl;
        } else {
            slot = (blk - 5120) * 256 + threadIdx.x;
            src = Wp; hi = g_WpBh; lo = g_WpBl;
        }
        int frag = slot >> 5, la = slot & 31;
        int n = ((frag >> 6) << 3) + (la >> 2);
        int k = ((frag & 63) << 4) + ((la & 3) << 1);
        const float* p = src + (size_t)n * 1024 + k;
        float2 x0 = *(const float2*)p;
        float2 x1 = *(const float2*)(p + 8);
        uint2 h, l;
        split2(x0, h.x, l.x);
        split2(x1, h.y, l.y);
        hi[slot] = h;
        lo[slot] = l;
    }
}

// ===========================================================================
// GEMM via mma.sync, warp tile 64x64, 4 warps (2x2), 2 CTAs/SM.
// (unchanged — proven 72% tensor)
// ===========================================================================
#define GSTAGE 32768
#define GSMEM  (3 * GSTAGE)

__global__ __launch_bounds__(128, 2)
void gemm_bf(const uint4* __restrict__ Ah, const uint4* __restrict__ Al,
             const uint2* __restrict__ Bh, const uint2* __restrict__ Bl,
             const float* __restrict__ bias, float* __restrict__ Cout,
             int N, int mode)
{
    extern __shared__ char smem[];
    const uint32_t sb = smem_u32(smem);
    const int tid = threadIdx.x;
    const int la  = tid & 31;
    const int wrp = tid >> 5;   // 0..3
    const int wm  = wrp >> 1;   // 0..1
    const int wn  = wrp & 1;    // 0..1
    const int r16b = blockIdx.y * 8;
    const int n8b  = blockIdx.x * 16;

    float acc[4][8][4];
#pragma unroll
    for (int i = 0; i < 4; i++)
#pragma unroll
        for (int j = 0; j < 8; j++)
#pragma unroll
            for (int r = 0; r < 4; r++) acc[i][j][r] = 0.f;

    auto issue = [&](int stage, int kc) {
        uint32_t base = sb + stage * GSTAGE;
#pragma unroll
        for (int rep = 0; rep < 4; rep++) {
            int u = rep * 128 + tid;           // 0..511
            int f = u >> 5, ln = u & 31;
            int ga = ((r16b + (f >> 1)) << 6) + (kc << 1) + (f & 1);
            CP16(base + f * 512 + ln * 16,        Ah + (size_t)ga * 32 + ln);
            CP16(base + 8192 + f * 512 + ln * 16, Al + (size_t)ga * 32 + ln);
        }
#pragma unroll
        for (int rep = 0; rep < 4; rep++) {
            int u = rep * 128 + tid;           // 0..511
            int f = u >> 4, j = u & 15;
            int gb = ((n8b + (f >> 1)) << 6) + (kc << 1) + (f & 1);
            CP16(base + 16384 + f * 256 + j * 16,
                 (const uint4*)Bh + (size_t)gb * 16 + j);
            CP16(base + 24576 + f * 256 + j * 16,
                 (const uint4*)Bl + (size_t)gb * 16 + j);
        }
        CP_COMMIT();
    };

    auto compute = [&](int stage) {
        char* base = smem + stage * GSTAGE;
#pragma unroll
        for (int kf = 0; kf < 2; kf++) {
            uint4 ah[4], al[4];
#pragma unroll
            for (int i = 0; i < 4; i++) {
                int foff = ((wm * 4 + i) * 2 + kf) * 512 + la * 16;
                ah[i] = *(const uint4*)(base + foff);
                al[i] = *(const uint4*)(base + 8192 + foff);
            }
#pragma unroll
            for (int jg = 0; jg < 2; jg++) {
                uint2 bh[4], bl[4];
#pragma unroll
                for (int jj = 0; jj < 4; jj++) {
                    int boff = ((wn * 8 + jg * 4 + jj) * 2 + kf) * 256 + la * 8;
                    bh[jj] = *(const uint2*)(base + 16384 + boff);
                    bl[jj] = *(const uint2*)(base + 24576 + boff);
                }
#pragma unroll
                for (int i = 0; i < 4; i++)
#pragma unroll
                    for (int jj = 0; jj < 4; jj++) {
                        float* a = acc[i][jg * 4 + jj];
                        mma16816(a, ah[i], bh[jj]);
                        mma16816(a, ah[i], bl[jj]);
                        mma16816(a, al[i], bh[jj]);
                    }
            }
        }
    };

    issue(0, 0);
    issue(1, 1);

    for (int kc = 0; kc < 32; kc++) {
        if (kc + 2 < 32) {
            issue((kc + 2) % 3, kc + 2);
            CP_WAIT2();
        } else if (kc + 1 < 32) {
            CP_WAIT1();
        } else {
            CP_WAIT0();
        }
        __syncthreads();
        compute(kc % 3);
        __syncthreads();
    }

    const int brow = blockIdx.y * 128;
    const int bcol = blockIdx.x * 128;

    if (mode == 0) {
        // plain fp32 epilogue (+bias)
#pragma unroll
        for (int j = 0; j < 8; j++) {
            int c0 = bcol + wn * 64 + j * 8 + (la & 3) * 2;
            float bx = 0.f, by = 0.f;
            if (bias) { bx = bias[c0]; by = bias[c0 + 1]; }
#pragma unroll
            for (int i = 0; i < 4; i++) {
                int r0 = brow + wm * 64 + i * 16 + (la >> 2);
                float2 o0, o1;
                o0.x = acc[i][j][0] + bx; o0.y = acc[i][j][1] + by;
                o1.x = acc[i][j][2] + bx; o1.y = acc[i][j][3] + by;
                *(float2*)&Cout[(size_t)r0 * N + c0]       = o0;
                *(float2*)&Cout[(size_t)(r0 + 8) * N + c0] = o1;
            }
        }
    } else {
        // fused kqv epilogue. cols [0,1024)=k, [1024,2048)=q, [2048,3072)=v
        int role = bcol >> 10;
        if (role == 2) {
            // V: stage acc fp32 to smem, transpose, write V B-frag planes.
            float* VS = (float*)smem;   // [128][132] floats
#pragma unroll
            for (int j = 0; j < 8; j++) {
                int c0 = wn * 64 + j * 8 + (la & 3) * 2;
#pragma unroll
                for (int i = 0; i < 4; i++) {
                    int r0 = wm * 64 + i * 16 + (la >> 2);
                    VS[r0 * 132 + c0]           = acc[i][j][0];
                    VS[r0 * 132 + c0 + 1]       = acc[i][j][1];
                    VS[(r0 + 8) * 132 + c0]     = acc[i][j][2];
                    VS[(r0 + 8) * 132 + c0 + 1] = acc[i][j][3];
                }
            }
            __syncthreads();
            int b     = brow >> 11;
            int trow  = brow & 2047;
            int hbase = (bcol - 2048) >> 6;
#pragma unroll
            for (int it = 0; it < 32; it++) {
                int f   = it * 4 + wrp;          // 0..127 local frag
                int kf2 = f & 3;
                int nf  = (f >> 2) & 7;
                int ktl = (f >> 5) & 1;
                int hh  = f >> 6;
                int dl  = hh * 64 + nf * 8 + (la >> 2);
                int kl  = ktl * 64 + kf2 * 16 + (la & 3) * 2;
                float v00 = VS[kl * 132 + dl];
                float v01 = VS[(kl + 1) * 132 + dl];
                float v10 = VS[(kl + 8) * 132 + dl];
                float v11 = VS[(kl + 9) * 132 + dl];
                uint2 vh, vl;
                split2(make_float2(v00, v01), vh.x, vl.x);
                split2(make_float2(v10, v11), vh.y, vl.y);
                int BH = b * 16 + hbase + hh;
                int kt = (trow >> 6) + ktl;
                size_t slot = (size_t)(BH * 32 + kt) * 1024 + (nf * 4 + kf2) * 32 + la;
                g_VBh[slot] = vh;
                g_VBl[slot] = vl;
            }
        } else {
#pragma unroll
            for (int t = 0; t < 4; t++) {
                int gcol = (bcol & 1023) + wn * 64 + t * 16;
                int h  = gcol >> 6;
                int kf = (gcol >> 4) & 3;
#pragma unroll
                for (int i = 0; i < 4; i++) {
                    int grow = brow + wm * 64 + i * 16;
                    int b = grow >> 11, trow = grow & 2047;
                    int BH = b * 16 + h;
                    const float* a0 = acc[i][2 * t];
                    const float* a1 = acc[i][2 * t + 1];
                    if (role == 1) {
                        // Q A-frag, scale QSCALE
                        size_t slot = ((((size_t)BH * 128) + (trow >> 4)) * 4 + kf) * 32 + la;
                        uint4 ah4, al4;
                        split2(make_float2(a0[0] * QSCALE, a0[1] * QSCALE), ah4.x, al4.x);
                        split2(make_float2(a0[2] * QSCALE, a0[3] * QSCALE), ah4.y, al4.y);
                        split2(make_float2(a1[0] * QSCALE, a1[1] * QSCALE), ah4.z, al4.z);
                        split2(make_float2(a1[2] * QSCALE, a1[3] * QSCALE), ah4.w, al4.w);
                        g_QAh[slot] = ah4;
                        g_QAl[slot] = al4;
                    } else {
                        // K B-frags
                        int kt = trow >> 6;
                        size_t fb = ((size_t)BH * 32 + kt) * 8;
                        size_t s0 = ((fb + 2 * i)     * 4 + kf) * 32 + la;
                        size_t s1 = ((fb + 2 * i + 1) * 4 + kf) * 32 + la;
                        uint2 h0, l0, h1, l1;
                        split2(make_float2(a0[0], a0[1]), h0.x, l0.x);
                        split2(make_float2(a1[0], a1[1]), h0.y, l0.y);
                        split2(make_float2(a0[2], a0[3]), h1.x, l1.x);
                        split2(make_float2(a1[2], a1[3]), h1.y, l1.y);
                        g_KBh[s0] = h0; g_KBl[s0] = l0;
                        g_KBh[s1] = h1; g_KBl[s1] = l1;
                    }
                }
            }
        }
    }
}

// ===========================================================================
// Flash attention v6: 256 q-rows per CTA, 512 threads (16 warps), 1 CTA/SM.
// Halves K/V tile loads vs 128-row CTAs (4608 CTA-tiles instead of 8704).
// smem: stage0 [0,32K) stage1 [32K,64K): KH | KL | VH | VL (8KB each)
//       QH [64K, 96K), QL [96K, 128K)   (256 rows x 4 kf x 512B per plane)
// ===========================================================================
#define ASTAGE   32768
#define AQH_OFF  65536
#define AQL_OFF  98304
#define ATTN_SMEM 131072

__global__ __launch_bounds__(512, 1)
void attn_mma6()
{
    const int qt = 7 - blockIdx.x;    // heavy CTAs first (qt' 0..7)
    const int h  = blockIdx.y;
    const int b  = blockIdx.z;
    const int BH = b * 16 + h;

    extern __shared__ char smem[];
    const uint32_t sb = smem_u32(smem);

    const int tid = threadIdx.x;
    const int la  = tid & 31;
    const int w   = tid >> 5;         // 0..15
    const int r_in  = la >> 2;
    const int cpair = (la & 3) * 2;
    const int qbase = qt * 256;
    const int row0  = qbase + w * 16 + r_in;
    const int row1  = row0 + 8;

    // --- issue Q fragments (one cp.async group, stays resident) ---
    {
        size_t qb = ((size_t)BH * 128 + qt * 16) * 128;   // uint4 units (16 q16-rows)
#pragma unroll
        for (int rep = 0; rep < 4; rep++) {
            int u = rep * 512 + tid;                       // 0..2047
            CP16(sb + AQH_OFF + u * 16, g_QAh + qb + u);
            CP16(sb + AQL_OFF + u * 16, g_QAl + qb + u);
        }
        CP_COMMIT();
    }

    auto issue_tile = [&](int stage, int kt) {
        uint32_t base = sb + stage * ASTAGE;
        size_t t = ((size_t)BH * 32 + kt) * 512;   // uint4 units per plane-tile
        int u = tid;                               // 0..511, one unit per plane
        CP16(base + u * 16,         (const uint4*)g_KBh + t + u);
        CP16(base + 8192 + u * 16,  (const uint4*)g_KBl + t + u);
        CP16(base + 16384 + u * 16, (const uint4*)g_VBh + t + u);
        CP16(base + 24576 + u * 16, (const uint4*)g_VBl + t + u);
        CP_COMMIT();
    };

    float o[8][4];
#pragma unroll
    for (int nf = 0; nf < 8; nf++)
#pragma unroll
        for (int r = 0; r < 4; r++) o[nf][r] = 0.f;
    float m0 = -1e30f, m1 = -1e30f, l0 = 0.f, l1 = 0.f;

    const int ntiles = 4 * qt + 4;
    issue_tile(0, 0);

    for (int kt = 0; kt < ntiles; kt++) {
        if (kt + 1 < ntiles) {
            issue_tile((kt + 1) & 1, kt + 1);
            CP_WAIT1();
        } else {
            CP_WAIT0();
        }
        __syncthreads();

        char* stg = smem + (kt & 1) * ASTAGE;
        const int kbase = kt * 64;

        if (kbase <= qbase + w * 16 + 15) {
            // --- S = Q K^T  (split-3; Q from smem) ---
            float sfr[8][4];
#pragma unroll
            for (int nf = 0; nf < 8; nf++)
#pragma unroll
                for (int r = 0; r < 4; r++) sfr[nf][r] = 0.f;

#pragma unroll
            for (int kf = 0; kf < 4; kf++) {
                int qoff = ((w * 4 + kf) << 9) + (la << 4);
                uint4 qh = *(const uint4*)(smem + AQH_OFF + qoff);
                uint4 ql = *(const uint4*)(smem + AQL_OFF + qoff);
#pragma unroll
                for (int nf = 0; nf < 8; nf++) {
                    int off = ((nf * 4 + kf) << 8) + (la << 3);
                    uint2 kh = *(const uint2*)(stg + off);
                    uint2 kl = *(const uint2*)(stg + 8192 + off);
                    mma16816(sfr[nf], qh, kh);
                    mma16816(sfr[nf], qh, kl);
                    mma16816(sfr[nf], ql, kh);
                }
            }

            // --- causal mask (near-diagonal tiles only) ---
            if (kbase + 63 > qbase + w * 16) {
#pragma unroll
                for (int nf = 0; nf < 8; nf++) {
                    int c = kbase + nf * 8 + cpair;
                    if (c     > row0) sfr[nf][0] = -1e30f;
                    if (c + 1 > row0) sfr[nf][1] = -1e30f;
                    if (c     > row1) sfr[nf][2] = -1e30f;
                    if (c + 1 > row1) sfr[nf][3] = -1e30f;
                }
            }

            // --- online softmax (exp2 domain) ---
            float mx0 = -1e30f, mx1 = -1e30f;
#pragma unroll
            for (int nf = 0; nf < 8; nf++) {
                mx0 = fmaxf(mx0, fmaxf(sfr[nf][0], sfr[nf][1]));
                mx1 = fmaxf(mx1, fmaxf(sfr[nf][2], sfr[nf][3]));
            }
            mx0 = fmaxf(mx0, __shfl_xor_sync(0xffffffffu, mx0, 1));
            mx0 = fmaxf(mx0, __shfl_xor_sync(0xffffffffu, mx0, 2));
            mx1 = fmaxf(mx1, __shfl_xor_sync(0xffffffffu, mx1, 1));
            mx1 = fmaxf(mx1, __shfl_xor_sync(0xffffffffu, mx1, 2));

            float mn0 = fmaxf(m0, mx0), mn1 = fmaxf(m1, mx1);
            float a0 = ex2(m0 - mn0), a1 = ex2(m1 - mn1);
            float s0 = 0.f, s1 = 0.f;
#pragma unroll
            for (int nf = 0; nf < 8; nf++) {
                sfr[nf][0] = ex2(sfr[nf][0] - mn0);
                sfr[nf][1] = ex2(sfr[nf][1] - mn0);
                sfr[nf][2] = ex2(sfr[nf][2] - mn1);
                sfr[nf][3] = ex2(sfr[nf][3] - mn1);
                s0 += sfr[nf][0] + sfr[nf][1];
                s1 += sfr[nf][2] + sfr[nf][3];
            }
            s0 += __shfl_xor_sync(0xffffffffu, s0, 1);
            s0 += __shfl_xor_sync(0xffffffffu, s0, 2);
            s1 += __shfl_xor_sync(0xffffffffu, s1, 1);
            s1 += __shfl_xor_sync(0xffffffffu, s1, 2);

            l0 = l0 * a0 + s0;  l1 = l1 * a1 + s1;
            m0 = mn0;           m1 = mn1;
#pragma unroll
            for (int nf = 0; nf < 8; nf++) {
                o[nf][0] *= a0; o[nf][1] *= a0;
                o[nf][2] *= a1; o[nf][3] *= a1;
            }

            // --- O += P V  (register-retag P; split-3) ---
#pragma unroll
            for (int kf2 = 0; kf2 < 4; kf2++) {
                uint4 Ph, Pl;
                split2(make_float2(sfr[2 * kf2][0],     sfr[2 * kf2][1]),     Ph.x, Pl.x);
                split2(make_float2(sfr[2 * kf2][2],     sfr[2 * kf2][3]),     Ph.y, Pl.y);
                split2(make_float2(sfr[2 * kf2 + 1][0], sfr[2 * kf2 + 1][1]), Ph.z, Pl.z);
                split2(make_float2(sfr[2 * kf2 + 1][2], sfr[2 * kf2 + 1][3]), Ph.w, Pl.w);
#pragma unroll
                for (int nf = 0; nf < 8; nf++) {
                    int off = ((nf * 4 + kf2) << 8) + (la << 3);
                    uint2 vh = *(const uint2*)(stg + 16384 + off);
                    uint2 vl = *(const uint2*)(stg + 24576 + off);
                    mma16816(o[nf], Ph, vh);
                    mma16816(o[nf], Ph, vl);
                    mma16816(o[nf], Pl, vh);
                }
            }
        }
        __syncthreads();
    }

    // --- epilogue: write gemm2 A-frag planes directly (o / l) ---
    float i0 = 1.f / l0, i1 = 1.f / l1;
    const int r16 = b * 128 + qt * 16 + w;
#pragma unroll
    for (int nf = 0; nf < 8; nf += 2) {
        int kfg = h * 4 + (nf >> 1);
        size_t slot = ((size_t)r16 * 64 + kfg) * 32 + la;
        uint4 ah4, al4;
        split2(make_float2(o[nf][0] * i0,     o[nf][1] * i0),     ah4.x, al4.x);
        split2(make_float2(o[nf][2] * i1,     o[nf][3] * i1),     ah4.y, al4.y);
        split2(make_float2(o[nf + 1][0] * i0, o[nf + 1][1] * i0), ah4.z, al4.z);
        split2(make_float2(o[nf + 1][2] * i1, o[nf + 1][3] * i1), ah4.w, al4.w);
        g_atAh[slot] = ah4;
        g_atAl[slot] = al4;
    }
}

// ---------------------------------------------------------------------------
// Launch
// ---------------------------------------------------------------------------
extern "C" void kernel_launch(void* const* d_in, const int* in_sizes, int n_in,
                              void* d_out, int out_size)
{
    const float* x = nullptr, *Wkqv = nullptr, *Wproj = nullptr, *bproj = nullptr;
    for (int i = 0; i < n_in; i++) {
        int sz = in_sizes[i];
        if      (sz == TB * TT * NE)      x     = (const float*)d_in[i];
        else if (sz == 3 * NE * NE)       Wkqv  = (const float*)d_in[i];
        else if (sz == NE * NE)           Wproj = (const float*)d_in[i];
        else if (sz == NE)                bproj = (const float*)d_in[i];
    }
    float* out = (float*)d_out;

    uint4 *xAh, *xAl, *atAh, *atAl;
    uint2 *WkBh, *WkBl, *WpBh, *WpBl;
    cudaGetSymbolAddress((void**)&xAh,  g_xAh);
    cudaGetSymbolAddress((void**)&xAl,  g_xAl);
    cudaGetSymbolAddress((void**)&atAh, g_atAh);
    cudaGetSymbolAddress((void**)&atAl, g_atAl);
    cudaGetSymbolAddress((void**)&WkBh, g_WkBh);
    cudaGetSymbolAddress((void**)&WkBl, g_WkBl);
    cudaGetSymbolAddress((void**)&WpBh, g_WpBh);
    cudaGetSymbolAddress((void**)&WpBl, g_WpBl);

    cudaFuncSetAttribute(gemm_bf,
                         cudaFuncAttributeMaxDynamicSharedMemorySize, GSMEM);
    cudaFuncSetAttribute(attn_mma6,
                         cudaFuncAttributeMaxDynamicSharedMemorySize, ATTN_SMEM);

    // Prep inputs: fragment-major bf16 hi/lo (single launch)
    prep_all<<<6144, 256>>>(x, Wkqv, Wproj);

    // 1) KQV projection, fused epilogue -> Q/K/V fragment planes
    {
        dim3 grid(C3 / 128, 32);
        gemm_bf<<<grid, 128, GSMEM>>>(xAh, xAl, WkBh, WkBl, nullptr, out, NE, 1);
    }

    // 2) Causal flash attention -> g_atA planes
    {
        dim3 grid(TT / 256, NH, TB);
        attn_mma6<<<grid, 512, ATTN_SMEM>>>();
    }

    // 3) Output projection + bias
    {
        dim3 grid(NE / 128, 32);
        gemm_bf<<<grid, 128, GSMEM>>>(atAh, atAl, WpBh, WpBl, bproj, out, NE, 0);
    }
}

// round 13
// speedup vs baseline: 1.0535x; 1.0535x over previous
#include <cuda_runtime.h>
#include <cuda_bf16.h>
#include <math.h>
#include <stddef.h>
#include <stdint.h>

// Problem constants
#define TB 2
#define TT 2048
#define NE 1024
#define NH 16
#define HD 64
#define C3 (3 * NE)   // 3072

// Q scale: 1/sqrt(64) * log2(e)  (softmax runs in exp2 domain)
#define QSCALE 0.18033688011112042f

// Fragment-major bf16 hi/lo planes (mma register layout in gmem).
__device__ uint4 g_xAh [(size_t)256 * 64 * 32];   // x      A-frags
__device__ uint4 g_xAl [(size_t)256 * 64 * 32];
__device__ uint4 g_atAh[(size_t)256 * 64 * 32];   // attn out A-frags (gemm2 input)
__device__ uint4 g_atAl[(size_t)256 * 64 * 32];
__device__ uint2 g_WkBh[(size_t)384 * 64 * 32];   // W_kqv  B-frags
__device__ uint2 g_WkBl[(size_t)384 * 64 * 32];
__device__ uint2 g_WpBh[(size_t)128 * 64 * 32];   // W_proj B-frags
__device__ uint2 g_WpBl[(size_t)128 * 64 * 32];

// Attention planes, per (b,h):
__device__ uint4 g_QAh[(size_t)32 * 128 * 4 * 32];
__device__ uint4 g_QAl[(size_t)32 * 128 * 4 * 32];
__device__ uint2 g_KBh[(size_t)32 * 32 * 8 * 4 * 32];
__device__ uint2 g_KBl[(size_t)32 * 32 * 8 * 4 * 32];
__device__ uint2 g_VBh[(size_t)32 * 32 * 8 * 4 * 32];
__device__ uint2 g_VBl[(size_t)32 * 32 * 8 * 4 * 32];

// ===========================================================================
// PTX helpers
// ===========================================================================
static __device__ __forceinline__ void mma16816(float* d, const uint4& a, const uint2& b) {
    asm volatile(
        "mma.sync.aligned.m16n8k16.row.col.f32.bf16.bf16.f32 "
        "{%0,%1,%2,%3}, {%4,%5,%6,%7}, {%8,%9}, {%0,%1,%2,%3};"
        : "+f"(d[0]), "+f"(d[1]), "+f"(d[2]), "+f"(d[3])
        : "r"(a.x), "r"(a.y), "r"(a.z), "r"(a.w), "r"(b.x), "r"(b.y));
}

static __device__ __forceinline__ void split2(float2 f, uint32_t& h, uint32_t& l) {
    __nv_bfloat162 hp = __floats2bfloat162_rn(f.x, f.y);
    float2 hf = __bfloat1622float2(hp);
    __nv_bfloat162 lp = __floats2bfloat162_rn(f.x - hf.x, f.y - hf.y);
    h = *reinterpret_cast<uint32_t*>(&hp);
    l = *reinterpret_cast<uint32_t*>(&lp);
}

static __device__ __forceinline__ float ex2(float x) {
    float r;
    asm("ex2.approx.f32 %0, %1;" : "=f"(r) : "f"(x));
    return r;
}

static __device__ __forceinline__ uint32_t smem_u32(const void* p) {
    uint32_t a;
    asm("{ .reg .u64 t; cvta.to.shared.u64 t, %1; cvt.u32.u64 %0, t; }"
        : "=r"(a) : "l"(p));
    return a;
}

#define CP16(dst, src) \
    asm volatile("cp.async.cg.shared.global [%0], [%1], 16;" :: "r"(dst), "l"(src))
#define CP_COMMIT() asm volatile("cp.async.commit_group;" ::: "memory")
#define CP_WAIT2()  asm volatile("cp.async.wait_group 2;" ::: "memory")
#define CP_WAIT1()  asm volatile("cp.async.wait_group 1;" ::: "memory")
#define CP_WAIT0()  asm volatile("cp.async.wait_group 0;" ::: "memory")

// ===========================================================================
// Merged prep kernel: one launch converts x (A-frags), W_kqv, W_proj (B-frags)
//   blocks [0,2048)      : x -> g_xA*
//   blocks [2048,5120)   : W_kqv -> g_WkB*
//   blocks [5120,6144)   : W_proj -> g_WpB*
// ===========================================================================
__global__ __launch_bounds__(256)
void prep_all(const float* __restrict__ x, const float* __restrict__ Wk,
              const float* __restrict__ Wp)
{
    int blk = blockIdx.x;
    if (blk < 2048) {
        int slot = blk * 256 + threadIdx.x;
        int frag = slot >> 5, la = slot & 31;
        int row = ((frag >> 6) << 4) + (la >> 2);
        int k   = ((frag & 63) << 4) + ((la & 3) << 1);
        const float* p = x + (size_t)row * 1024 + k;
        float2 x0 = *(const float2*)p;
        float2 x1 = *(const float2*)(p + 8 * 1024);
        float2 x2 = *(const float2*)(p + 8);
        float2 x3 = *(const float2*)(p + 8 * 1024 + 8);
        uint4 h, l;
        split2(x0, h.x, l.x);
        split2(x1, h.y, l.y);
        split2(x2, h.z, l.z);
        split2(x3, h.w, l.w);
        g_xAh[slot] = h;
        g_xAl[slot] = l;
    } else {
        const float* src;
        uint2 *hi, *lo;
        int slot;
        if (blk < 5120) {
            slot = (blk - 2048) * 256 + threadIdx.x;
            src = Wk; hi = g_WkBh; lo = g_WkBl;
        } else {
            slot = (blk - 5120) * 256 + threadIdx.x;
            src = Wp; hi = g_WpBh; lo = g_WpBl;
        }
        int frag = slot >> 5, la = slot & 31;
        int n = ((frag >> 6) << 3) + (la >> 2);
        int k = ((frag & 63) << 4) + ((la & 3) << 1);
        const float* p = src + (size_t)n * 1024 + k;
        float2 x0 = *(const float2*)p;
        float2 x1 = *(const float2*)(p + 8);
        uint2 h, l;
        split2(x0, h.x, l.x);
        split2(x1, h.y, l.y);
        hi[slot] = h;
        lo[slot] = l;
    }
}

// ===========================================================================
// GEMM via mma.sync, warp tile 64x64, 4 warps (2x2), 2 CTAs/SM.
// (unchanged — proven 72% tensor)
// ===========================================================================
#define GSTAGE 32768
#define GSMEM  (3 * GSTAGE)

__global__ __launch_bounds__(128, 2)
void gemm_bf(const uint4* __restrict__ Ah, const uint4* __restrict__ Al,
             const uint2* __restrict__ Bh, const uint2* __restrict__ Bl,
             const float* __restrict__ bias, float* __restrict__ Cout,
             int N, int mode)
{
    extern __shared__ char smem[];
    const uint32_t sb = smem_u32(smem);
    const int tid = threadIdx.x;
    const int la  = tid & 31;
    const int wrp = tid >> 5;   // 0..3
    const int wm  = wrp >> 1;   // 0..1
    const int wn  = wrp & 1;    // 0..1
    const int r16b = blockIdx.y * 8;
    const int n8b  = blockIdx.x * 16;

    float acc[4][8][4];
#pragma unroll
    for (int i = 0; i < 4; i++)
#pragma unroll
        for (int j = 0; j < 8; j++)
#pragma unroll
            for (int r = 0; r < 4; r++) acc[i][j][r] = 0.f;

    auto issue = [&](int stage, int kc) {
        uint32_t base = sb + stage * GSTAGE;
#pragma unroll
        for (int rep = 0; rep < 4; rep++) {
            int u = rep * 128 + tid;           // 0..511
            int f = u >> 5, ln = u & 31;
            int ga = ((r16b + (f >> 1)) << 6) + (kc << 1) + (f & 1);
            CP16(base + f * 512 + ln * 16,        Ah + (size_t)ga * 32 + ln);
            CP16(base + 8192 + f * 512 + ln * 16, Al + (size_t)ga * 32 + ln);
        }
#pragma unroll
        for (int rep = 0; rep < 4; rep++) {
            int u = rep * 128 + tid;           // 0..511
            int f = u >> 4, j = u & 15;
            int gb = ((n8b + (f >> 1)) << 6) + (kc << 1) + (f & 1);
            CP16(base + 16384 + f * 256 + j * 16,
                 (const uint4*)Bh + (size_t)gb * 16 + j);
            CP16(base + 24576 + f * 256 + j * 16,
                 (const uint4*)Bl + (size_t)gb * 16 + j);
        }
        CP_COMMIT();
    };

    auto compute = [&](int stage) {
        char* base = smem + stage * GSTAGE;
#pragma unroll
        for (int kf = 0; kf < 2; kf++) {
            uint4 ah[4], al[4];
#pragma unroll
            for (int i = 0; i < 4; i++) {
                int foff = ((wm * 4 + i) * 2 + kf) * 512 + la * 16;
                ah[i] = *(const uint4*)(base + foff);
                al[i] = *(const uint4*)(base + 8192 + foff);
            }
#pragma unroll
            for (int jg = 0; jg < 2; jg++) {
                uint2 bh[4], bl[4];
#pragma unroll
                for (int jj = 0; jj < 4; jj++) {
                    int boff = ((wn * 8 + jg * 4 + jj) * 2 + kf) * 256 + la * 8;
                    bh[jj] = *(const uint2*)(base + 16384 + boff);
                    bl[jj] = *(const uint2*)(base + 24576 + boff);
                }
#pragma unroll
                for (int i = 0; i < 4; i++)
#pragma unroll
                    for (int jj = 0; jj < 4; jj++) {
                        float* a = acc[i][jg * 4 + jj];
                        mma16816(a, ah[i], bh[jj]);
                        mma16816(a, ah[i], bl[jj]);
                        mma16816(a, al[i], bh[jj]);
                    }
            }
        }
    };

    issue(0, 0);
    issue(1, 1);

    for (int kc = 0; kc < 32; kc++) {
        if (kc + 2 < 32) {
            issue((kc + 2) % 3, kc + 2);
            CP_WAIT2();
        } else if (kc + 1 < 32) {
            CP_WAIT1();
        } else {
            CP_WAIT0();
        }
        __syncthreads();
        compute(kc % 3);
        __syncthreads();
    }

    const int brow = blockIdx.y * 128;
    const int bcol = blockIdx.x * 128;

    if (mode == 0) {
        // plain fp32 epilogue (+bias)
#pragma unroll
        for (int j = 0; j < 8; j++) {
            int c0 = bcol + wn * 64 + j * 8 + (la & 3) * 2;
            float bx = 0.f, by = 0.f;
            if (bias) { bx = bias[c0]; by = bias[c0 + 1]; }
#pragma unroll
            for (int i = 0; i < 4; i++) {
                int r0 = brow + wm * 64 + i * 16 + (la >> 2);
                float2 o0, o1;
                o0.x = acc[i][j][0] + bx; o0.y = acc[i][j][1] + by;
                o1.x = acc[i][j][2] + bx; o1.y = acc[i][j][3] + by;
                *(float2*)&Cout[(size_t)r0 * N + c0]       = o0;
                *(float2*)&Cout[(size_t)(r0 + 8) * N + c0] = o1;
            }
        }
    } else {
        // fused kqv epilogue. cols [0,1024)=k, [1024,2048)=q, [2048,3072)=v
        int role = bcol >> 10;
        if (role == 2) {
            // V: stage acc fp32 to smem, transpose, write V B-frag planes.
            float* VS = (float*)smem;   // [128][132] floats
#pragma unroll
            for (int j = 0; j < 8; j++) {
                int c0 = wn * 64 + j * 8 + (la & 3) * 2;
#pragma unroll
                for (int i = 0; i < 4; i++) {
                    int r0 = wm * 64 + i * 16 + (la >> 2);
                    VS[r0 * 132 + c0]           = acc[i][j][0];
                    VS[r0 * 132 + c0 + 1]       = acc[i][j][1];
                    VS[(r0 + 8) * 132 + c0]     = acc[i][j][2];
                    VS[(r0 + 8) * 132 + c0 + 1] = acc[i][j][3];
                }
            }
            __syncthreads();
            int b     = brow >> 11;
            int trow  = brow & 2047;
            int hbase = (bcol - 2048) >> 6;
#pragma unroll
            for (int it = 0; it < 32; it++) {
                int f   = it * 4 + wrp;          // 0..127 local frag
                int kf2 = f & 3;
                int nf  = (f >> 2) & 7;
                int ktl = (f >> 5) & 1;
                int hh  = f >> 6;
                int dl  = hh * 64 + nf * 8 + (la >> 2);
                int kl  = ktl * 64 + kf2 * 16 + (la & 3) * 2;
                float v00 = VS[kl * 132 + dl];
                float v01 = VS[(kl + 1) * 132 + dl];
                float v10 = VS[(kl + 8) * 132 + dl];
                float v11 = VS[(kl + 9) * 132 + dl];
                uint2 vh, vl;
                split2(make_float2(v00, v01), vh.x, vl.x);
                split2(make_float2(v10, v11), vh.y, vl.y);
                int BH = b * 16 + hbase + hh;
                int kt = (trow >> 6) + ktl;
                size_t slot = (size_t)(BH * 32 + kt) * 1024 + (nf * 4 + kf2) * 32 + la;
                g_VBh[slot] = vh;
                g_VBl[slot] = vl;
            }
        } else {
#pragma unroll
            for (int t = 0; t < 4; t++) {
                int gcol = (bcol & 1023) + wn * 64 + t * 16;
                int h  = gcol >> 6;
                int kf = (gcol >> 4) & 3;
#pragma unroll
                for (int i = 0; i < 4; i++) {
                    int grow = brow + wm * 64 + i * 16;
                    int b = grow >> 11, trow = grow & 2047;
                    int BH = b * 16 + h;
                    const float* a0 = acc[i][2 * t];
                    const float* a1 = acc[i][2 * t + 1];
                    if (role == 1) {
                        // Q A-frag, scale QSCALE
                        size_t slot = ((((size_t)BH * 128) + (trow >> 4)) * 4 + kf) * 32 + la;
                        uint4 ah4, al4;
                        split2(make_float2(a0[0] * QSCALE, a0[1] * QSCALE), ah4.x, al4.x);
                        split2(make_float2(a0[2] * QSCALE, a0[3] * QSCALE), ah4.y, al4.y);
                        split2(make_float2(a1[0] * QSCALE, a1[1] * QSCALE), ah4.z, al4.z);
                        split2(make_float2(a1[2] * QSCALE, a1[3] * QSCALE), ah4.w, al4.w);
                        g_QAh[slot] = ah4;
                        g_QAl[slot] = al4;
                    } else {
                        // K B-frags
                        int kt = trow >> 6;
                        size_t fb = ((size_t)BH * 32 + kt) * 8;
                        size_t s0 = ((fb + 2 * i)     * 4 + kf) * 32 + la;
                        size_t s1 = ((fb + 2 * i + 1) * 4 + kf) * 32 + la;
                        uint2 h0, l0, h1, l1;
                        split2(make_float2(a0[0], a0[1]), h0.x, l0.x);
                        split2(make_float2(a1[0], a1[1]), h0.y, l0.y);
                        split2(make_float2(a0[2], a0[3]), h1.x, l1.x);
                        split2(make_float2(a1[2], a1[3]), h1.y, l1.y);
                        g_KBh[s0] = h0; g_KBl[s0] = l0;
                        g_KBh[s1] = h1; g_KBl[s1] = l1;
                    }
                }
            }
        }
    }
}

// ===========================================================================
// Flash attention (round-11 winner): Q frags in SMEM, 128 q-rows/CTA,
// 256 threads, 2 CTAs/SM, 2-stage cp.async K/V tiles, exp2 softmax,
// whole-warp tile skip, direct A-frag epilogue.
// smem: stage0 [0,32K) stage1 [32K,64K): KH | KL | VH | VL (8KB each)
//       QH [64K, 80K), QL [80K, 96K)
// ===========================================================================
#define ASTAGE   32768
#define AQH_OFF  65536
#define AQL_OFF  81920
#define ATTN_SMEM 98304

__global__ __launch_bounds__(256, 2)
void attn_mma5()
{
    const int qt = 15 - blockIdx.x;   // heavy CTAs first
    const int h  = blockIdx.y;
    const int b  = blockIdx.z;
    const int BH = b * 16 + h;

    extern __shared__ char smem[];
    const uint32_t sb = smem_u32(smem);

    const int tid = threadIdx.x;
    const int la  = tid & 31;
    const int w   = tid >> 5;
    const int r_in  = la >> 2;
    const int cpair = (la & 3) * 2;
    const int qbase = qt * 128;
    const int row0  = qbase + w * 16 + r_in;
    const int row1  = row0 + 8;

    // --- issue Q fragments (one cp.async group, stays resident) ---
    {
        size_t qb = ((size_t)BH * 128 + qt * 8) * 128;   // uint4 units
#pragma unroll
        for (int rep = 0; rep < 4; rep++) {
            int u = rep * 256 + tid;                      // 0..1023
            CP16(sb + AQH_OFF + u * 16, g_QAh + qb + u);
            CP16(sb + AQL_OFF + u * 16, g_QAl + qb + u);
        }
        CP_COMMIT();
    }

    auto issue_tile = [&](int stage, int kt) {
        uint32_t base = sb + stage * ASTAGE;
        size_t t = ((size_t)BH * 32 + kt) * 512;
#pragma unroll
        for (int rep = 0; rep < 2; rep++) {
            int u = rep * 256 + tid;
            CP16(base + u * 16,         (const uint4*)g_KBh + t + u);
            CP16(base + 8192 + u * 16,  (const uint4*)g_KBl + t + u);
            CP16(base + 16384 + u * 16, (const uint4*)g_VBh + t + u);
            CP16(base + 24576 + u * 16, (const uint4*)g_VBl + t + u);
        }
        CP_COMMIT();
    };

    float o[8][4];
#pragma unroll
    for (int nf = 0; nf < 8; nf++)
#pragma unroll
        for (int r = 0; r < 4; r++) o[nf][r] = 0.f;
    float m0 = -1e30f, m1 = -1e30f, l0 = 0.f, l1 = 0.f;

    const int ntiles = 2 * qt + 2;
    issue_tile(0, 0);

    for (int kt = 0; kt < ntiles; kt++) {
        if (kt + 1 < ntiles) {
            issue_tile((kt + 1) & 1, kt + 1);
            CP_WAIT1();
        } else {
            CP_WAIT0();
        }
        __syncthreads();

        char* stg = smem + (kt & 1) * ASTAGE;
        const int kbase = kt * 64;

        if (kbase <= qbase + w * 16 + 15) {
            // --- S = Q K^T  (split-3; Q from smem, per-kf LDS) ---
            float sfr[8][4];
#pragma unroll
            for (int nf = 0; nf < 8; nf++)
#pragma unroll
                for (int r = 0; r < 4; r++) sfr[nf][r] = 0.f;

#pragma unroll
            for (int kf = 0; kf < 4; kf++) {
                int qoff = ((w * 4 + kf) << 9) + (la << 4);
                uint4 qh = *(const uint4*)(smem + AQH_OFF + qoff);
                uint4 ql = *(const uint4*)(smem + AQL_OFF + qoff);
#pragma unroll
                for (int nf = 0; nf < 8; nf++) {
                    int off = ((nf * 4 + kf) << 8) + (la << 3);
                    uint2 kh = *(const uint2*)(stg + off);
                    uint2 kl = *(const uint2*)(stg + 8192 + off);
                    mma16816(sfr[nf], qh, kh);
                    mma16816(sfr[nf], qh, kl);
                    mma16816(sfr[nf], ql, kh);
                }
            }

            // --- causal mask (near-diagonal tiles only) ---
            if (kbase + 63 > qbase + w * 16) {
#pragma unroll
                for (int nf = 0; nf < 8; nf++) {
                    int c = kbase + nf * 8 + cpair;
                    if (c     > row0) sfr[nf][0] = -1e30f;
                    if (c + 1 > row0) sfr[nf][1] = -1e30f;
                    if (c     > row1) sfr[nf][2] = -1e30f;
                    if (c + 1 > row1) sfr[nf][3] = -1e30f;
                }
            }

            // --- online softmax (exp2 domain) ---
            float mx0 = -1e30f, mx1 = -1e30f;
#pragma unroll
            for (int nf = 0; nf < 8; nf++) {
                mx0 = fmaxf(mx0, fmaxf(sfr[nf][0], sfr[nf][1]));
                mx1 = fmaxf(mx1, fmaxf(sfr[nf][2], sfr[nf][3]));
            }
            mx0 = fmaxf(mx0, __shfl_xor_sync(0xffffffffu, mx0, 1));
            mx0 = fmaxf(mx0, __shfl_xor_sync(0xffffffffu, mx0, 2));
            mx1 = fmaxf(mx1, __shfl_xor_sync(0xffffffffu, mx1, 1));
            mx1 = fmaxf(mx1, __shfl_xor_sync(0xffffffffu, mx1, 2));

            float mn0 = fmaxf(m0, mx0), mn1 = fmaxf(m1, mx1);
            float a0 = ex2(m0 - mn0), a1 = ex2(m1 - mn1);
            float s0 = 0.f, s1 = 0.f;
#pragma unroll
            for (int nf = 0; nf < 8; nf++) {
                sfr[nf][0] = ex2(sfr[nf][0] - mn0);
                sfr[nf][1] = ex2(sfr[nf][1] - mn0);
                sfr[nf][2] = ex2(sfr[nf][2] - mn1);
                sfr[nf][3] = ex2(sfr[nf][3] - mn1);
                s0 += sfr[nf][0] + sfr[nf][1];
                s1 += sfr[nf][2] + sfr[nf][3];
            }
            s0 += __shfl_xor_sync(0xffffffffu, s0, 1);
            s0 += __shfl_xor_sync(0xffffffffu, s0, 2);
            s1 += __shfl_xor_sync(0xffffffffu, s1, 1);
            s1 += __shfl_xor_sync(0xffffffffu, s1, 2);

            l0 = l0 * a0 + s0;  l1 = l1 * a1 + s1;
            m0 = mn0;           m1 = mn1;
#pragma unroll
            for (int nf = 0; nf < 8; nf++) {
                o[nf][0] *= a0; o[nf][1] *= a0;
                o[nf][2] *= a1; o[nf][3] *= a1;
            }

            // --- O += P V  (register-retag P; split-3) ---
#pragma unroll
            for (int kf2 = 0; kf2 < 4; kf2++) {
                uint4 Ph, Pl;
                split2(make_float2(sfr[2 * kf2][0],     sfr[2 * kf2][1]),     Ph.x, Pl.x);
                split2(make_float2(sfr[2 * kf2][2],     sfr[2 * kf2][3]),     Ph.y, Pl.y);
                split2(make_float2(sfr[2 * kf2 + 1][0], sfr[2 * kf2 + 1][1]), Ph.z, Pl.z);
                split2(make_float2(sfr[2 * kf2 + 1][2], sfr[2 * kf2 + 1][3]), Ph.w, Pl.w);
#pragma unroll
                for (int nf = 0; nf < 8; nf++) {
                    int off = ((nf * 4 + kf2) << 8) + (la << 3);
                    uint2 vh = *(const uint2*)(stg + 16384 + off);
                    uint2 vl = *(const uint2*)(stg + 24576 + off);
                    mma16816(o[nf], Ph, vh);
                    mma16816(o[nf], Ph, vl);
                    mma16816(o[nf], Pl, vh);
                }
            }
        }
        __syncthreads();
    }

    // --- epilogue: write gemm2 A-frag planes directly (o / l) ---
    float i0 = 1.f / l0, i1 = 1.f / l1;
    const int r16 = b * 128 + qt * 8 + w;
#pragma unroll
    for (int nf = 0; nf < 8; nf += 2) {
        int kfg = h * 4 + (nf >> 1);
        size_t slot = ((size_t)r16 * 64 + kfg) * 32 + la;
        uint4 ah4, al4;
        split2(make_float2(o[nf][0] * i0,     o[nf][1] * i0),     ah4.x, al4.x);
        split2(make_float2(o[nf][2] * i1,     o[nf][3] * i1),     ah4.y, al4.y);
        split2(make_float2(o[nf + 1][0] * i0, o[nf + 1][1] * i0), ah4.z, al4.z);
        split2(make_float2(o[nf + 1][2] * i1, o[nf + 1][3] * i1), ah4.w, al4.w);
        g_atAh[slot] = ah4;
        g_atAl[slot] = al4;
    }
}

// ---------------------------------------------------------------------------
// Launch
// ---------------------------------------------------------------------------
extern "C" void kernel_launch(void* const* d_in, const int* in_sizes, int n_in,
                              void* d_out, int out_size)
{
    const float* x = nullptr, *Wkqv = nullptr, *Wproj = nullptr, *bproj = nullptr;
    for (int i = 0; i < n_in; i++) {
        int sz = in_sizes[i];
        if      (sz == TB * TT * NE)      x     = (const float*)d_in[i];
        else if (sz == 3 * NE * NE)       Wkqv  = (const float*)d_in[i];
        else if (sz == NE * NE)           Wproj = (const float*)d_in[i];
        else if (sz == NE)                bproj = (const float*)d_in[i];
    }
    float* out = (float*)d_out;

    uint4 *xAh, *xAl, *atAh, *atAl;
    uint2 *WkBh, *WkBl, *WpBh, *WpBl;
    cudaGetSymbolAddress((void**)&xAh,  g_xAh);
    cudaGetSymbolAddress((void**)&xAl,  g_xAl);
    cudaGetSymbolAddress((void**)&atAh, g_atAh);
    cudaGetSymbolAddress((void**)&atAl, g_atAl);
    cudaGetSymbolAddress((void**)&WkBh, g_WkBh);
    cudaGetSymbolAddress((void**)&WkBl, g_WkBl);
    cudaGetSymbolAddress((void**)&WpBh, g_WpBh);
    cudaGetSymbolAddress((void**)&WpBl, g_WpBl);

    cudaFuncSetAttribute(gemm_bf,
                         cudaFuncAttributeMaxDynamicSharedMemorySize, GSMEM);
    cudaFuncSetAttribute(attn_mma5,
                         cudaFuncAttributeMaxDynamicSharedMemorySize, ATTN_SMEM);

    // Prep inputs: fragment-major bf16 hi/lo (single launch)
    prep_all<<<6144, 256>>>(x, Wkqv, Wproj);

    // 1) KQV projection, fused epilogue -> Q/K/V fragment planes
    {
        dim3 grid(C3 / 128, 32);
        gemm_bf<<<grid, 128, GSMEM>>>(xAh, xAl, WkBh, WkBl, nullptr, out, NE, 1);
    }

    // 2) Causal flash attention -> g_atA planes
    {
        dim3 grid(TT / 128, NH, TB);
        attn_mma5<<<grid, 256, ATTN_SMEM>>>();
    }

    // 3) Output projection + bias
    {
        dim3 grid(NE / 128, 32);
        gemm_bf<<<grid, 128, GSMEM>>>(atAh, atAl, WpBh, WpBl, bproj, out, NE, 0);
    }
}

// round 14
// speedup vs baseline: 1.0605x; 1.0067x over previous
#include <cuda_runtime.h>
#include <cuda_bf16.h>
#include <math.h>
#include <stddef.h>
#include <stdint.h>

// Problem constants
#define TB 2
#define TT 2048
#define NE 1024
#define NH 16
#define HD 64
#define C3 (3 * NE)   // 3072

// Q scale: 1/sqrt(64) * log2(e)  (softmax runs in exp2 domain)
#define QSCALE 0.18033688011112042f

// Fragment-major bf16 hi/lo planes (mma register layout in gmem).
__device__ uint4 g_xAh [(size_t)256 * 64 * 32];   // x      A-frags
__device__ uint4 g_xAl [(size_t)256 * 64 * 32];
__device__ uint4 g_atAh[(size_t)256 * 64 * 32];   // attn out A-frags (gemm2 input)
__device__ uint4 g_atAl[(size_t)256 * 64 * 32];
__device__ uint2 g_WkBh[(size_t)384 * 64 * 32];   // W_kqv  B-frags
__device__ uint2 g_WkBl[(size_t)384 * 64 * 32];
__device__ uint2 g_WpBh[(size_t)128 * 64 * 32];   // W_proj B-frags
__device__ uint2 g_WpBl[(size_t)128 * 64 * 32];

// Attention planes, per (b,h):
__device__ uint4 g_QAh[(size_t)32 * 128 * 4 * 32];
__device__ uint4 g_QAl[(size_t)32 * 128 * 4 * 32];
__device__ uint2 g_KBh[(size_t)32 * 32 * 8 * 4 * 32];
__device__ uint2 g_KBl[(size_t)32 * 32 * 8 * 4 * 32];
__device__ uint2 g_VBh[(size_t)32 * 32 * 8 * 4 * 32];
__device__ uint2 g_VBl[(size_t)32 * 32 * 8 * 4 * 32];

// ===========================================================================
// PTX helpers
// ===========================================================================
static __device__ __forceinline__ void mma16816(float* d, const uint4& a, const uint2& b) {
    asm volatile(
        "mma.sync.aligned.m16n8k16.row.col.f32.bf16.bf16.f32 "
        "{%0,%1,%2,%3}, {%4,%5,%6,%7}, {%8,%9}, {%0,%1,%2,%3};"
        : "+f"(d[0]), "+f"(d[1]), "+f"(d[2]), "+f"(d[3])
        : "r"(a.x), "r"(a.y), "r"(a.z), "r"(a.w), "r"(b.x), "r"(b.y));
}

static __device__ __forceinline__ void split2(float2 f, uint32_t& h, uint32_t& l) {
    __nv_bfloat162 hp = __floats2bfloat162_rn(f.x, f.y);
    float2 hf = __bfloat1622float2(hp);
    __nv_bfloat162 lp = __floats2bfloat162_rn(f.x - hf.x, f.y - hf.y);
    h = *reinterpret_cast<uint32_t*>(&hp);
    l = *reinterpret_cast<uint32_t*>(&lp);
}

static __device__ __forceinline__ float ex2(float x) {
    float r;
    asm("ex2.approx.f32 %0, %1;" : "=f"(r) : "f"(x));
    return r;
}

static __device__ __forceinline__ uint32_t smem_u32(const void* p) {
    uint32_t a;
    asm("{ .reg .u64 t; cvta.to.shared.u64 t, %1; cvt.u32.u64 %0, t; }"
        : "=r"(a) : "l"(p));
    return a;
}

#define CP16(dst, src) \
    asm volatile("cp.async.cg.shared.global [%0], [%1], 16;" :: "r"(dst), "l"(src))
#define CP_COMMIT() asm volatile("cp.async.commit_group;" ::: "memory")
#define CP_WAIT2()  asm volatile("cp.async.wait_group 2;" ::: "memory")
#define CP_WAIT1()  asm volatile("cp.async.wait_group 1;" ::: "memory")
#define CP_WAIT0()  asm volatile("cp.async.wait_group 0;" ::: "memory")

// ===========================================================================
// Merged prep kernel: one launch converts x (A-frags), W_kqv, W_proj (B-frags)
// ===========================================================================
__global__ __launch_bounds__(256)
void prep_all(const float* __restrict__ x, const float* __restrict__ Wk,
              const float* __restrict__ Wp)
{
    int blk = blockIdx.x;
    if (blk < 2048) {
        int slot = blk * 256 + threadIdx.x;
        int frag = slot >> 5, la = slot & 31;
        int row = ((frag >> 6) << 4) + (la >> 2);
        int k   = ((frag & 63) << 4) + ((la & 3) << 1);
        const float* p = x + (size_t)row * 1024 + k;
        float2 x0 = *(const float2*)p;
        float2 x1 = *(const float2*)(p + 8 * 1024);
        float2 x2 = *(const float2*)(p + 8);
        float2 x3 = *(const float2*)(p + 8 * 1024 + 8);
        uint4 h, l;
        split2(x0, h.x, l.x);
        split2(x1, h.y, l.y);
        split2(x2, h.z, l.z);
        split2(x3, h.w, l.w);
        g_xAh[slot] = h;
        g_xAl[slot] = l;
    } else {
        const float* src;
        uint2 *hi, *lo;
        int slot;
        if (blk < 5120) {
            slot = (blk - 2048) * 256 + threadIdx.x;
            src = Wk; hi = g_WkBh; lo = g_WkBl;
        } else {
            slot = (blk - 5120) * 256 + threadIdx.x;
            src = Wp; hi = g_WpBh; lo = g_WpBl;
        }
        int frag = slot >> 5, la = slot & 31;
        int n = ((frag >> 6) << 3) + (la >> 2);
        int k = ((frag & 63) << 4) + ((la & 3) << 1);
        const float* p = src + (size_t)n * 1024 + k;
        float2 x0 = *(const float2*)p;
        float2 x1 = *(const float2*)(p + 8);
        uint2 h, l;
        split2(x0, h.x, l.x);
        split2(x1, h.y, l.y);
        hi[slot] = h;
        lo[slot] = l;
    }
}

// ===========================================================================
// GEMM via mma.sync, warp tile 64x64, 4 warps (2x2), 2 CTAs/SM.
// MMA issue order: term-major (hh pass, hl pass, lh pass) to break
// accumulator RAW chains (revisit distance 16 MMAs).
// ===========================================================================
#define GSTAGE 32768
#define GSMEM  (3 * GSTAGE)

__global__ __launch_bounds__(128, 2)
void gemm_bf(const uint4* __restrict__ Ah, const uint4* __restrict__ Al,
             const uint2* __restrict__ Bh, const uint2* __restrict__ Bl,
             const float* __restrict__ bias, float* __restrict__ Cout,
             int N, int mode)
{
    extern __shared__ char smem[];
    const uint32_t sb = smem_u32(smem);
    const int tid = threadIdx.x;
    const int la  = tid & 31;
    const int wrp = tid >> 5;   // 0..3
    const int wm  = wrp >> 1;   // 0..1
    const int wn  = wrp & 1;    // 0..1
    const int r16b = blockIdx.y * 8;
    const int n8b  = blockIdx.x * 16;

    float acc[4][8][4];
#pragma unroll
    for (int i = 0; i < 4; i++)
#pragma unroll
        for (int j = 0; j < 8; j++)
#pragma unroll
            for (int r = 0; r < 4; r++) acc[i][j][r] = 0.f;

    auto issue = [&](int stage, int kc) {
        uint32_t base = sb + stage * GSTAGE;
#pragma unroll
        for (int rep = 0; rep < 4; rep++) {
            int u = rep * 128 + tid;           // 0..511
            int f = u >> 5, ln = u & 31;
            int ga = ((r16b + (f >> 1)) << 6) + (kc << 1) + (f & 1);
            CP16(base + f * 512 + ln * 16,        Ah + (size_t)ga * 32 + ln);
            CP16(base + 8192 + f * 512 + ln * 16, Al + (size_t)ga * 32 + ln);
        }
#pragma unroll
        for (int rep = 0; rep < 4; rep++) {
            int u = rep * 128 + tid;           // 0..511
            int f = u >> 4, j = u & 15;
            int gb = ((n8b + (f >> 1)) << 6) + (kc << 1) + (f & 1);
            CP16(base + 16384 + f * 256 + j * 16,
                 (const uint4*)Bh + (size_t)gb * 16 + j);
            CP16(base + 24576 + f * 256 + j * 16,
                 (const uint4*)Bl + (size_t)gb * 16 + j);
        }
        CP_COMMIT();
    };

    auto compute = [&](int stage) {
        char* base = smem + stage * GSTAGE;
#pragma unroll
        for (int kf = 0; kf < 2; kf++) {
            uint4 ah[4], al[4];
#pragma unroll
            for (int i = 0; i < 4; i++) {
                int foff = ((wm * 4 + i) * 2 + kf) * 512 + la * 16;
                ah[i] = *(const uint4*)(base + foff);
                al[i] = *(const uint4*)(base + 8192 + foff);
            }
#pragma unroll
            for (int jg = 0; jg < 2; jg++) {
                uint2 bh[4], bl[4];
#pragma unroll
                for (int jj = 0; jj < 4; jj++) {
                    int boff = ((wn * 8 + jg * 4 + jj) * 2 + kf) * 256 + la * 8;
                    bh[jj] = *(const uint2*)(base + 16384 + boff);
                    bl[jj] = *(const uint2*)(base + 24576 + boff);
                }
                // term-major passes: acc revisit distance = 16 MMAs
#pragma unroll
                for (int i = 0; i < 4; i++)
#pragma unroll
                    for (int jj = 0; jj < 4; jj++)
                        mma16816(acc[i][jg * 4 + jj], ah[i], bh[jj]);
#pragma unroll
                for (int i = 0; i < 4; i++)
#pragma unroll
                    for (int jj = 0; jj < 4; jj++)
                        mma16816(acc[i][jg * 4 + jj], ah[i], bl[jj]);
#pragma unroll
                for (int i = 0; i < 4; i++)
#pragma unroll
                    for (int jj = 0; jj < 4; jj++)
                        mma16816(acc[i][jg * 4 + jj], al[i], bh[jj]);
            }
        }
    };

    issue(0, 0);
    issue(1, 1);

    for (int kc = 0; kc < 32; kc++) {
        if (kc + 2 < 32) {
            issue((kc + 2) % 3, kc + 2);
            CP_WAIT2();
        } else if (kc + 1 < 32) {
            CP_WAIT1();
        } else {
            CP_WAIT0();
        }
        __syncthreads();
        compute(kc % 3);
        __syncthreads();
    }

    const int brow = blockIdx.y * 128;
    const int bcol = blockIdx.x * 128;

    if (mode == 0) {
        // plain fp32 epilogue (+bias)
#pragma unroll
        for (int j = 0; j < 8; j++) {
            int c0 = bcol + wn * 64 + j * 8 + (la & 3) * 2;
            float bx = 0.f, by = 0.f;
            if (bias) { bx = bias[c0]; by = bias[c0 + 1]; }
#pragma unroll
            for (int i = 0; i < 4; i++) {
                int r0 = brow + wm * 64 + i * 16 + (la >> 2);
                float2 o0, o1;
                o0.x = acc[i][j][0] + bx; o0.y = acc[i][j][1] + by;
                o1.x = acc[i][j][2] + bx; o1.y = acc[i][j][3] + by;
                *(float2*)&Cout[(size_t)r0 * N + c0]       = o0;
                *(float2*)&Cout[(size_t)(r0 + 8) * N + c0] = o1;
            }
        }
    } else {
        // fused kqv epilogue. cols [0,1024)=k, [1024,2048)=q, [2048,3072)=v
        int role = bcol >> 10;
        if (role == 2) {
            // V: stage acc fp32 to smem, transpose, write V B-frag planes.
            float* VS = (float*)smem;   // [128][132] floats
#pragma unroll
            for (int j = 0; j < 8; j++) {
                int c0 = wn * 64 + j * 8 + (la & 3) * 2;
#pragma unroll
                for (int i = 0; i < 4; i++) {
                    int r0 = wm * 64 + i * 16 + (la >> 2);
                    VS[r0 * 132 + c0]           = acc[i][j][0];
                    VS[r0 * 132 + c0 + 1]       = acc[i][j][1];
                    VS[(r0 + 8) * 132 + c0]     = acc[i][j][2];
                    VS[(r0 + 8) * 132 + c0 + 1] = acc[i][j][3];
                }
            }
            __syncthreads();
            int b     = brow >> 11;
            int trow  = brow & 2047;
            int hbase = (bcol - 2048) >> 6;
#pragma unroll
            for (int it = 0; it < 32; it++) {
                int f   = it * 4 + wrp;          // 0..127 local frag
                int kf2 = f & 3;
                int nf  = (f >> 2) & 7;
                int ktl = (f >> 5) & 1;
                int hh  = f >> 6;
                int dl  = hh * 64 + nf * 8 + (la >> 2);
                int kl  = ktl * 64 + kf2 * 16 + (la & 3) * 2;
                float v00 = VS[kl * 132 + dl];
                float v01 = VS[(kl + 1) * 132 + dl];
                float v10 = VS[(kl + 8) * 132 + dl];
                float v11 = VS[(kl + 9) * 132 + dl];
                uint2 vh, vl;
                split2(make_float2(v00, v01), vh.x, vl.x);
                split2(make_float2(v10, v11), vh.y, vl.y);
                int BH = b * 16 + hbase + hh;
                int kt = (trow >> 6) + ktl;
                size_t slot = (size_t)(BH * 32 + kt) * 1024 + (nf * 4 + kf2) * 32 + la;
                g_VBh[slot] = vh;
                g_VBl[slot] = vl;
            }
        } else {
#pragma unroll
            for (int t = 0; t < 4; t++) {
                int gcol = (bcol & 1023) + wn * 64 + t * 16;
                int h  = gcol >> 6;
                int kf = (gcol >> 4) & 3;
#pragma unroll
                for (int i = 0; i < 4; i++) {
                    int grow = brow + wm * 64 + i * 16;
                    int b = grow >> 11, trow = grow & 2047;
                    int BH = b * 16 + h;
                    const float* a0 = acc[i][2 * t];
                    const float* a1 = acc[i][2 * t + 1];
                    if (role == 1) {
                        // Q A-frag, scale QSCALE
                        size_t slot = ((((size_t)BH * 128) + (trow >> 4)) * 4 + kf) * 32 + la;
                        uint4 ah4, al4;
                        split2(make_float2(a0[0] * QSCALE, a0[1] * QSCALE), ah4.x, al4.x);
                        split2(make_float2(a0[2] * QSCALE, a0[3] * QSCALE), ah4.y, al4.y);
                        split2(make_float2(a1[0] * QSCALE, a1[1] * QSCALE), ah4.z, al4.z);
                        split2(make_float2(a1[2] * QSCALE, a1[3] * QSCALE), ah4.w, al4.w);
                        g_QAh[slot] = ah4;
                        g_QAl[slot] = al4;
                    } else {
                        // K B-frags
                        int kt = trow >> 6;
                        size_t fb = ((size_t)BH * 32 + kt) * 8;
                        size_t s0 = ((fb + 2 * i)     * 4 + kf) * 32 + la;
                        size_t s1 = ((fb + 2 * i + 1) * 4 + kf) * 32 + la;
                        uint2 h0, l0, h1, l1;
                        split2(make_float2(a0[0], a0[1]), h0.x, l0.x);
                        split2(make_float2(a1[0], a1[1]), h0.y, l0.y);
                        split2(make_float2(a0[2], a0[3]), h1.x, l1.x);
                        split2(make_float2(a1[2], a1[3]), h1.y, l1.y);
                        g_KBh[s0] = h0; g_KBl[s0] = l0;
                        g_KBh[s1] = h1; g_KBl[s1] = l1;
                    }
                }
            }
        }
    }
}

// ===========================================================================
// Flash attention: Q frags in SMEM, 128 q-rows/CTA, 256 threads, 2 CTAs/SM.
// MMA issue order term-major (chain-breaking); fragment reloaded in 3rd pass.
// ===========================================================================
#define ASTAGE   32768
#define AQH_OFF  65536
#define AQL_OFF  81920
#define ATTN_SMEM 98304

__global__ __launch_bounds__(256, 2)
void attn_mma5()
{
    const int qt = 15 - blockIdx.x;   // heavy CTAs first
    const int h  = blockIdx.y;
    const int b  = blockIdx.z;
    const int BH = b * 16 + h;

    extern __shared__ char smem[];
    const uint32_t sb = smem_u32(smem);

    const int tid = threadIdx.x;
    const int la  = tid & 31;
    const int w   = tid >> 5;
    const int r_in  = la >> 2;
    const int cpair = (la & 3) * 2;
    const int qbase = qt * 128;
    const int row0  = qbase + w * 16 + r_in;
    const int row1  = row0 + 8;

    // --- issue Q fragments (one cp.async group, stays resident) ---
    {
        size_t qb = ((size_t)BH * 128 + qt * 8) * 128;   // uint4 units
#pragma unroll
        for (int rep = 0; rep < 4; rep++) {
            int u = rep * 256 + tid;                      // 0..1023
            CP16(sb + AQH_OFF + u * 16, g_QAh + qb + u);
            CP16(sb + AQL_OFF + u * 16, g_QAl + qb + u);
        }
        CP_COMMIT();
    }

    auto issue_tile = [&](int stage, int kt) {
        uint32_t base = sb + stage * ASTAGE;
        size_t t = ((size_t)BH * 32 + kt) * 512;
#pragma unroll
        for (int rep = 0; rep < 2; rep++) {
            int u = rep * 256 + tid;
            CP16(base + u * 16,         (const uint4*)g_KBh + t + u);
            CP16(base + 8192 + u * 16,  (const uint4*)g_KBl + t + u);
            CP16(base + 16384 + u * 16, (const uint4*)g_VBh + t + u);
            CP16(base + 24576 + u * 16, (const uint4*)g_VBl + t + u);
        }
        CP_COMMIT();
    };

    float o[8][4];
#pragma unroll
    for (int nf = 0; nf < 8; nf++)
#pragma unroll
        for (int r = 0; r < 4; r++) o[nf][r] = 0.f;
    float m0 = -1e30f, m1 = -1e30f, l0 = 0.f, l1 = 0.f;

    const int ntiles = 2 * qt + 2;
    issue_tile(0, 0);

    for (int kt = 0; kt < ntiles; kt++) {
        if (kt + 1 < ntiles) {
            issue_tile((kt + 1) & 1, kt + 1);
            CP_WAIT1();
        } else {
            CP_WAIT0();
        }
        __syncthreads();

        char* stg = smem + (kt & 1) * ASTAGE;
        const int kbase = kt * 64;

        if (kbase <= qbase + w * 16 + 15) {
            // --- S = Q K^T  (split-3; term-major passes per kf) ---
            float sfr[8][4];
#pragma unroll
            for (int nf = 0; nf < 8; nf++)
#pragma unroll
                for (int r = 0; r < 4; r++) sfr[nf][r] = 0.f;

#pragma unroll
            for (int kf = 0; kf < 4; kf++) {
                int qoff = ((w * 4 + kf) << 9) + (la << 4);
                uint4 qh = *(const uint4*)(smem + AQH_OFF + qoff);
                uint4 ql = *(const uint4*)(smem + AQL_OFF + qoff);
#pragma unroll
                for (int nf = 0; nf < 8; nf++) {
                    uint2 kh = *(const uint2*)(stg + ((nf * 4 + kf) << 8) + (la << 3));
                    mma16816(sfr[nf], qh, kh);
                }
#pragma unroll
                for (int nf = 0; nf < 8; nf++) {
                    uint2 kl = *(const uint2*)(stg + 8192 + ((nf * 4 + kf) << 8) + (la << 3));
                    mma16816(sfr[nf], qh, kl);
                }
#pragma unroll
                for (int nf = 0; nf < 8; nf++) {
                    uint2 kh = *(const uint2*)(stg + ((nf * 4 + kf) << 8) + (la << 3));
                    mma16816(sfr[nf], ql, kh);
                }
            }

            // --- causal mask (near-diagonal tiles only) ---
            if (kbase + 63 > qbase + w * 16) {
#pragma unroll
                for (int nf = 0; nf < 8; nf++) {
                    int c = kbase + nf * 8 + cpair;
                    if (c     > row0) sfr[nf][0] = -1e30f;
                    if (c + 1 > row0) sfr[nf][1] = -1e30f;
                    if (c     > row1) sfr[nf][2] = -1e30f;
                    if (c + 1 > row1) sfr[nf][3] = -1e30f;
                }
            }

            // --- online softmax (exp2 domain) ---
            float mx0 = -1e30f, mx1 = -1e30f;
#pragma unroll
            for (int nf = 0; nf < 8; nf++) {
                mx0 = fmaxf(mx0, fmaxf(sfr[nf][0], sfr[nf][1]));
                mx1 = fmaxf(mx1, fmaxf(sfr[nf][2], sfr[nf][3]));
            }
            mx0 = fmaxf(mx0, __shfl_xor_sync(0xffffffffu, mx0, 1));
            mx0 = fmaxf(mx0, __shfl_xor_sync(0xffffffffu, mx0, 2));
            mx1 = fmaxf(mx1, __shfl_xor_sync(0xffffffffu, mx1, 1));
            mx1 = fmaxf(mx1, __shfl_xor_sync(0xffffffffu, mx1, 2));

            float mn0 = fmaxf(m0, mx0), mn1 = fmaxf(m1, mx1);
            float a0 = ex2(m0 - mn0), a1 = ex2(m1 - mn1);
            float s0 = 0.f, s1 = 0.f;
#pragma unroll
            for (int nf = 0; nf < 8; nf++) {
                sfr[nf][0] = ex2(sfr[nf][0] - mn0);
                sfr[nf][1] = ex2(sfr[nf][1] - mn0);
                sfr[nf][2] = ex2(sfr[nf][2] - mn1);
                sfr[nf][3] = ex2(sfr[nf][3] - mn1);
                s0 += sfr[nf][0] + sfr[nf][1];
                s1 += sfr[nf][2] + sfr[nf][3];
            }
            s0 += __shfl_xor_sync(0xffffffffu, s0, 1);
            s0 += __shfl_xor_sync(0xffffffffu, s0, 2);
            s1 += __shfl_xor_sync(0xffffffffu, s1, 1);
            s1 += __shfl_xor_sync(0xffffffffu, s1, 2);

            l0 = l0 * a0 + s0;  l1 = l1 * a1 + s1;
            m0 = mn0;           m1 = mn1;
#pragma unroll
            for (int nf = 0; nf < 8; nf++) {
                o[nf][0] *= a0; o[nf][1] *= a0;
                o[nf][2] *= a1; o[nf][3] *= a1;
            }

            // --- O += P V  (register-retag P; term-major passes per kf2) ---
#pragma unroll
            for (int kf2 = 0; kf2 < 4; kf2++) {
                uint4 Ph, Pl;
                split2(make_float2(sfr[2 * kf2][0],     sfr[2 * kf2][1]),     Ph.x, Pl.x);
                split2(make_float2(sfr[2 * kf2][2],     sfr[2 * kf2][3]),     Ph.y, Pl.y);
                split2(make_float2(sfr[2 * kf2 + 1][0], sfr[2 * kf2 + 1][1]), Ph.z, Pl.z);
                split2(make_float2(sfr[2 * kf2 + 1][2], sfr[2 * kf2 + 1][3]), Ph.w, Pl.w);
#pragma unroll
                for (int nf = 0; nf < 8; nf++) {
                    uint2 vh = *(const uint2*)(stg + 16384 + ((nf * 4 + kf2) << 8) + (la << 3));
                    mma16816(o[nf], Ph, vh);
                }
#pragma unroll
                for (int nf = 0; nf < 8; nf++) {
                    uint2 vl = *(const uint2*)(stg + 24576 + ((nf * 4 + kf2) << 8) + (la << 3));
                    mma16816(o[nf], Ph, vl);
                }
#pragma unroll
                for (int nf = 0; nf < 8; nf++) {
                    uint2 vh = *(const uint2*)(stg + 16384 + ((nf * 4 + kf2) << 8) + (la << 3));
                    mma16816(o[nf], Pl, vh);
                }
            }
        }
        __syncthreads();
    }

    // --- epilogue: write gemm2 A-frag planes directly (o / l) ---
    float i0 = 1.f / l0, i1 = 1.f / l1;
    const int r16 = b * 128 + qt * 8 + w;
#pragma unroll
    for (int nf = 0; nf < 8; nf += 2) {
        int kfg = h * 4 + (nf >> 1);
        size_t slot = ((size_t)r16 * 64 + kfg) * 32 + la;
        uint4 ah4, al4;
        split2(make_float2(o[nf][0] * i0,     o[nf][1] * i0),     ah4.x, al4.x);
        split2(make_float2(o[nf][2] * i1,     o[nf][3] * i1),     ah4.y, al4.y);
        split2(make_float2(o[nf + 1][0] * i0, o[nf + 1][1] * i0), ah4.z, al4.z);
        split2(make_float2(o[nf + 1][2] * i1, o[nf + 1][3] * i1), ah4.w, al4.w);
        g_atAh[slot] = ah4;
        g_atAl[slot] = al4;
    }
}

// ---------------------------------------------------------------------------
// Launch
// ---------------------------------------------------------------------------
extern "C" void kernel_launch(void* const* d_in, const int* in_sizes, int n_in,
                              void* d_out, int out_size)
{
    const float* x = nullptr, *Wkqv = nullptr, *Wproj = nullptr, *bproj = nullptr;
    for (int i = 0; i < n_in; i++) {
        int sz = in_sizes[i];
        if      (sz == TB * TT * NE)      x     = (const float*)d_in[i];
        else if (sz == 3 * NE * NE)       Wkqv  = (const float*)d_in[i];
        else if (sz == NE * NE)           Wproj = (const float*)d_in[i];
        else if (sz == NE)                bproj = (const float*)d_in[i];
    }
    float* out = (float*)d_out;

    uint4 *xAh, *xAl, *atAh, *atAl;
    uint2 *WkBh, *WkBl, *WpBh, *WpBl;
    cudaGetSymbolAddress((void**)&xAh,  g_xAh);
    cudaGetSymbolAddress((void**)&xAl,  g_xAl);
    cudaGetSymbolAddress((void**)&atAh, g_atAh);
    cudaGetSymbolAddress((void**)&atAl, g_atAl);
    cudaGetSymbolAddress((void**)&WkBh, g_WkBh);
    cudaGetSymbolAddress((void**)&WkBl, g_WkBl);
    cudaGetSymbolAddress((void**)&WpBh, g_WpBh);
    cudaGetSymbolAddress((void**)&WpBl, g_WpBl);

    cudaFuncSetAttribute(gemm_bf,
                         cudaFuncAttributeMaxDynamicSharedMemorySize, GSMEM);
    cudaFuncSetAttribute(attn_mma5,
                         cudaFuncAttributeMaxDynamicSharedMemorySize, ATTN_SMEM);

    // Prep inputs: fragment-major bf16 hi/lo (single launch)
    prep_all<<<6144, 256>>>(x, Wkqv, Wproj);

    // 1) KQV projection, fused epilogue -> Q/K/V fragment planes
    {
        dim3 grid(C3 / 128, 32);
        gemm_bf<<<grid, 128, GSMEM>>>(xAh, xAl, WkBh, WkBl, nullptr, out, NE, 1);
    }

    // 2) Causal flash attention -> g_atA planes
    {
        dim3 grid(TT / 128, NH, TB);
        attn_mma5<<<grid, 256, ATTN_SMEM>>>();
    }

    // 3) Output projection + bias
    {
        dim3 grid(NE / 128, 32);
        gemm_bf<<<grid, 128, GSMEM>>>(atAh, atAl, WpBh, WpBl, bproj, out, NE, 0);
    }
}

// round 15
// speedup vs baseline: 1.1359x; 1.0711x over previous
#include <cuda_runtime.h>
#include <cuda_bf16.h>
#include <cuda_fp16.h>
#include <math.h>
#include <stddef.h>
#include <stdint.h>

// Problem constants
#define TB 2
#define TT 2048
#define NE 1024
#define NH 16
#define HD 64
#define C3 (3 * NE)   // 3072

// Q scale: 1/sqrt(64) * log2(e)  (softmax runs in exp2 domain)
#define QSCALE 0.18033688011112042f

// Fragment-major bf16 hi/lo planes (mma register layout in gmem).
__device__ uint4 g_xAh [(size_t)256 * 64 * 32];   // x      A-frags
__device__ uint4 g_xAl [(size_t)256 * 64 * 32];
__device__ uint4 g_atAh[(size_t)256 * 64 * 32];   // attn out A-frags (gemm2 input)
__device__ uint4 g_atAl[(size_t)256 * 64 * 32];
__device__ uint2 g_WkBh[(size_t)384 * 64 * 32];   // W_kqv  B-frags
__device__ uint2 g_WkBl[(size_t)384 * 64 * 32];
__device__ uint2 g_WpBh[(size_t)128 * 64 * 32];   // W_proj B-frags
__device__ uint2 g_WpBl[(size_t)128 * 64 * 32];

// Attention planes, per (b,h):
__device__ uint4 g_QAh[(size_t)32 * 128 * 4 * 32];   // bf16 hi/lo
__device__ uint4 g_QAl[(size_t)32 * 128 * 4 * 32];
__device__ uint2 g_KBh[(size_t)32 * 32 * 8 * 4 * 32]; // bf16 hi/lo
__device__ uint2 g_KBl[(size_t)32 * 32 * 8 * 4 * 32];
__device__ uint2 g_VBh[(size_t)32 * 32 * 8 * 4 * 32]; // fp16 hi/lo
__device__ uint2 g_VBl[(size_t)32 * 32 * 8 * 4 * 32];

// ===========================================================================
// PTX helpers
// ===========================================================================
static __device__ __forceinline__ void mma16816(float* d, const uint4& a, const uint2& b) {
    asm volatile(
        "mma.sync.aligned.m16n8k16.row.col.f32.bf16.bf16.f32 "
        "{%0,%1,%2,%3}, {%4,%5,%6,%7}, {%8,%9}, {%0,%1,%2,%3};"
        : "+f"(d[0]), "+f"(d[1]), "+f"(d[2]), "+f"(d[3])
        : "r"(a.x), "r"(a.y), "r"(a.z), "r"(a.w), "r"(b.x), "r"(b.y));
}

// fp16 variant (for P·V)
static __device__ __forceinline__ void mma16816h(float* d, const uint4& a, const uint2& b) {
    asm volatile(
        "mma.sync.aligned.m16n8k16.row.col.f32.f16.f16.f32 "
        "{%0,%1,%2,%3}, {%4,%5,%6,%7}, {%8,%9}, {%0,%1,%2,%3};"
        : "+f"(d[0]), "+f"(d[1]), "+f"(d[2]), "+f"(d[3])
        : "r"(a.x), "r"(a.y), "r"(a.z), "r"(a.w), "r"(b.x), "r"(b.y));
}

static __device__ __forceinline__ void split2(float2 f, uint32_t& h, uint32_t& l) {
    __nv_bfloat162 hp = __floats2bfloat162_rn(f.x, f.y);
    float2 hf = __bfloat1622float2(hp);
    __nv_bfloat162 lp = __floats2bfloat162_rn(f.x - hf.x, f.y - hf.y);
    h = *reinterpret_cast<uint32_t*>(&hp);
    l = *reinterpret_cast<uint32_t*>(&lp);
}

// fp16 hi/lo split (for V planes)
static __device__ __forceinline__ void hsplit2(float2 f, uint32_t& h, uint32_t& l) {
    __half2 hp = __floats2half2_rn(f.x, f.y);
    float2 hf = __half22float2(hp);
    __half2 lp = __floats2half2_rn(f.x - hf.x, f.y - hf.y);
    h = *reinterpret_cast<uint32_t*>(&hp);
    l = *reinterpret_cast<uint32_t*>(&lp);
}

static __device__ __forceinline__ uint32_t packh2(float a, float b) {
    __half2 p = __floats2half2_rn(a, b);
    return *reinterpret_cast<uint32_t*>(&p);
}

static __device__ __forceinline__ float ex2(float x) {
    float r;
    asm("ex2.approx.f32 %0, %1;" : "=f"(r) : "f"(x));
    return r;
}

static __device__ __forceinline__ uint32_t smem_u32(const void* p) {
    uint32_t a;
    asm("{ .reg .u64 t; cvta.to.shared.u64 t, %1; cvt.u32.u64 %0, t; }"
        : "=r"(a) : "l"(p));
    return a;
}

#define CP16(dst, src) \
    asm volatile("cp.async.cg.shared.global [%0], [%1], 16;" :: "r"(dst), "l"(src))
#define CP_COMMIT() asm volatile("cp.async.commit_group;" ::: "memory")
#define CP_WAIT2()  asm volatile("cp.async.wait_group 2;" ::: "memory")
#define CP_WAIT1()  asm volatile("cp.async.wait_group 1;" ::: "memory")
#define CP_WAIT0()  asm volatile("cp.async.wait_group 0;" ::: "memory")

// ===========================================================================
// Merged prep kernel
// ===========================================================================
__global__ __launch_bounds__(256)
void prep_all(const float* __restrict__ x, const float* __restrict__ Wk,
              const float* __restrict__ Wp)
{
    int blk = blockIdx.x;
    if (blk < 2048) {
        int slot = blk * 256 + threadIdx.x;
        int frag = slot >> 5, la = slot & 31;
        int row = ((frag >> 6) << 4) + (la >> 2);
        int k   = ((frag & 63) << 4) + ((la & 3) << 1);
        const float* p = x + (size_t)row * 1024 + k;
        float2 x0 = *(const float2*)p;
        float2 x1 = *(const float2*)(p + 8 * 1024);
        float2 x2 = *(const float2*)(p + 8);
        float2 x3 = *(const float2*)(p + 8 * 1024 + 8);
        uint4 h, l;
        split2(x0, h.x, l.x);
        split2(x1, h.y, l.y);
        split2(x2, h.z, l.z);
        split2(x3, h.w, l.w);
        g_xAh[slot] = h;
        g_xAl[slot] = l;
    } else {
        const float* src;
        uint2 *hi, *lo;
        int slot;
        if (blk < 5120) {
            slot = (blk - 2048) * 256 + threadIdx.x;
            src = Wk; hi = g_WkBh; lo = g_WkBl;
        } else {
            slot = (blk - 5120) * 256 + threadIdx.x;
            src = Wp; hi = g_WpBh; lo = g_WpBl;
        }
        int frag = slot >> 5, la = slot & 31;
        int n = ((frag >> 6) << 3) + (la >> 2);
        int k = ((frag & 63) << 4) + ((la & 3) << 1);
        const float* p = src + (size_t)n * 1024 + k;
        float2 x0 = *(const float2*)p;
        float2 x1 = *(const float2*)(p + 8);
        uint2 h, l;
        split2(x0, h.x, l.x);
        split2(x1, h.y, l.y);
        hi[slot] = h;
        lo[slot] = l;
    }
}

// ===========================================================================
// GEMM via mma.sync, warp tile 64x64, 4 warps (2x2), 2 CTAs/SM.
// ===========================================================================
#define GSTAGE 32768
#define GSMEM  (3 * GSTAGE)

__global__ __launch_bounds__(128, 2)
void gemm_bf(const uint4* __restrict__ Ah, const uint4* __restrict__ Al,
             const uint2* __restrict__ Bh, const uint2* __restrict__ Bl,
             const float* __restrict__ bias, float* __restrict__ Cout,
             int N, int mode)
{
    extern __shared__ char smem[];
    const uint32_t sb = smem_u32(smem);
    const int tid = threadIdx.x;
    const int la  = tid & 31;
    const int wrp = tid >> 5;   // 0..3
    const int wm  = wrp >> 1;   // 0..1
    const int wn  = wrp & 1;    // 0..1
    const int r16b = blockIdx.y * 8;
    const int n8b  = blockIdx.x * 16;

    float acc[4][8][4];
#pragma unroll
    for (int i = 0; i < 4; i++)
#pragma unroll
        for (int j = 0; j < 8; j++)
#pragma unroll
            for (int r = 0; r < 4; r++) acc[i][j][r] = 0.f;

    auto issue = [&](int stage, int kc) {
        uint32_t base = sb + stage * GSTAGE;
#pragma unroll
        for (int rep = 0; rep < 4; rep++) {
            int u = rep * 128 + tid;           // 0..511
            int f = u >> 5, ln = u & 31;
            int ga = ((r16b + (f >> 1)) << 6) + (kc << 1) + (f & 1);
            CP16(base + f * 512 + ln * 16,        Ah + (size_t)ga * 32 + ln);
            CP16(base + 8192 + f * 512 + ln * 16, Al + (size_t)ga * 32 + ln);
        }
#pragma unroll
        for (int rep = 0; rep < 4; rep++) {
            int u = rep * 128 + tid;           // 0..511
            int f = u >> 4, j = u & 15;
            int gb = ((n8b + (f >> 1)) << 6) + (kc << 1) + (f & 1);
            CP16(base + 16384 + f * 256 + j * 16,
                 (const uint4*)Bh + (size_t)gb * 16 + j);
            CP16(base + 24576 + f * 256 + j * 16,
                 (const uint4*)Bl + (size_t)gb * 16 + j);
        }
        CP_COMMIT();
    };

    auto compute = [&](int stage) {
        char* base = smem + stage * GSTAGE;
#pragma unroll
        for (int kf = 0; kf < 2; kf++) {
            uint4 ah[4], al[4];
#pragma unroll
            for (int i = 0; i < 4; i++) {
                int foff = ((wm * 4 + i) * 2 + kf) * 512 + la * 16;
                ah[i] = *(const uint4*)(base + foff);
                al[i] = *(const uint4*)(base + 8192 + foff);
            }
#pragma unroll
            for (int jg = 0; jg < 2; jg++) {
                uint2 bh[4], bl[4];
#pragma unroll
                for (int jj = 0; jj < 4; jj++) {
                    int boff = ((wn * 8 + jg * 4 + jj) * 2 + kf) * 256 + la * 8;
                    bh[jj] = *(const uint2*)(base + 16384 + boff);
                    bl[jj] = *(const uint2*)(base + 24576 + boff);
                }
#pragma unroll
                for (int i = 0; i < 4; i++)
#pragma unroll
                    for (int jj = 0; jj < 4; jj++)
                        mma16816(acc[i][jg * 4 + jj], ah[i], bh[jj]);
#pragma unroll
                for (int i = 0; i < 4; i++)
#pragma unroll
                    for (int jj = 0; jj < 4; jj++)
                        mma16816(acc[i][jg * 4 + jj], ah[i], bl[jj]);
#pragma unroll
                for (int i = 0; i < 4; i++)
#pragma unroll
                    for (int jj = 0; jj < 4; jj++)
                        mma16816(acc[i][jg * 4 + jj], al[i], bh[jj]);
            }
        }
    };

    issue(0, 0);
    issue(1, 1);

    for (int kc = 0; kc < 32; kc++) {
        if (kc + 2 < 32) {
            issue((kc + 2) % 3, kc + 2);
            CP_WAIT2();
        } else if (kc + 1 < 32) {
            CP_WAIT1();
        } else {
            CP_WAIT0();
        }
        __syncthreads();
        compute(kc % 3);
        __syncthreads();
    }

    const int brow = blockIdx.y * 128;
    const int bcol = blockIdx.x * 128;

    if (mode == 0) {
        // plain fp32 epilogue (+bias)
#pragma unroll
        for (int j = 0; j < 8; j++) {
            int c0 = bcol + wn * 64 + j * 8 + (la & 3) * 2;
            float bx = 0.f, by = 0.f;
            if (bias) { bx = bias[c0]; by = bias[c0 + 1]; }
#pragma unroll
            for (int i = 0; i < 4; i++) {
                int r0 = brow + wm * 64 + i * 16 + (la >> 2);
                float2 o0, o1;
                o0.x = acc[i][j][0] + bx; o0.y = acc[i][j][1] + by;
                o1.x = acc[i][j][2] + bx; o1.y = acc[i][j][3] + by;
                *(float2*)&Cout[(size_t)r0 * N + c0]       = o0;
                *(float2*)&Cout[(size_t)(r0 + 8) * N + c0] = o1;
            }
        }
    } else {
        // fused kqv epilogue. cols [0,1024)=k, [1024,2048)=q, [2048,3072)=v
        int role = bcol >> 10;
        if (role == 2) {
            // V: stage acc fp32 to smem, transpose, write fp16 V B-frag planes.
            float* VS = (float*)smem;   // [128][132] floats
#pragma unroll
            for (int j = 0; j < 8; j++) {
                int c0 = wn * 64 + j * 8 + (la & 3) * 2;
#pragma unroll
                for (int i = 0; i < 4; i++) {
                    int r0 = wm * 64 + i * 16 + (la >> 2);
                    VS[r0 * 132 + c0]           = acc[i][j][0];
                    VS[r0 * 132 + c0 + 1]       = acc[i][j][1];
                    VS[(r0 + 8) * 132 + c0]     = acc[i][j][2];
                    VS[(r0 + 8) * 132 + c0 + 1] = acc[i][j][3];
                }
            }
            __syncthreads();
            int b     = brow >> 11;
            int trow  = brow & 2047;
            int hbase = (bcol - 2048) >> 6;
#pragma unroll
            for (int it = 0; it < 32; it++) {
                int f   = it * 4 + wrp;          // 0..127 local frag
                int kf2 = f & 3;
                int nf  = (f >> 2) & 7;
                int ktl = (f >> 5) & 1;
                int hh  = f >> 6;
                int dl  = hh * 64 + nf * 8 + (la >> 2);
                int kl  = ktl * 64 + kf2 * 16 + (la & 3) * 2;
                float v00 = VS[kl * 132 + dl];
                float v01 = VS[(kl + 1) * 132 + dl];
                float v10 = VS[(kl + 8) * 132 + dl];
                float v11 = VS[(kl + 9) * 132 + dl];
                uint2 vh, vl;
                hsplit2(make_float2(v00, v01), vh.x, vl.x);
                hsplit2(make_float2(v10, v11), vh.y, vl.y);
                int BH = b * 16 + hbase + hh;
                int kt = (trow >> 6) + ktl;
                size_t slot = (size_t)(BH * 32 + kt) * 1024 + (nf * 4 + kf2) * 32 + la;
                g_VBh[slot] = vh;
                g_VBl[slot] = vl;
            }
        } else {
#pragma unroll
            for (int t = 0; t < 4; t++) {
                int gcol = (bcol & 1023) + wn * 64 + t * 16;
                int h  = gcol >> 6;
                int kf = (gcol >> 4) & 3;
#pragma unroll
                for (int i = 0; i < 4; i++) {
                    int grow = brow + wm * 64 + i * 16;
                    int b = grow >> 11, trow = grow & 2047;
                    int BH = b * 16 + h;
                    const float* a0 = acc[i][2 * t];
                    const float* a1 = acc[i][2 * t + 1];
                    if (role == 1) {
                        // Q A-frag, scale QSCALE
                        size_t slot = ((((size_t)BH * 128) + (trow >> 4)) * 4 + kf) * 32 + la;
                        uint4 ah4, al4;
                        split2(make_float2(a0[0] * QSCALE, a0[1] * QSCALE), ah4.x, al4.x);
                        split2(make_float2(a0[2] * QSCALE, a0[3] * QSCALE), ah4.y, al4.y);
                        split2(make_float2(a1[0] * QSCALE, a1[1] * QSCALE), ah4.z, al4.z);
                        split2(make_float2(a1[2] * QSCALE, a1[3] * QSCALE), ah4.w, al4.w);
                        g_QAh[slot] = ah4;
                        g_QAl[slot] = al4;
                    } else {
                        // K B-frags
                        int kt = trow >> 6;
                        size_t fb = ((size_t)BH * 32 + kt) * 8;
                        size_t s0 = ((fb + 2 * i)     * 4 + kf) * 32 + la;
                        size_t s1 = ((fb + 2 * i + 1) * 4 + kf) * 32 + la;
                        uint2 h0, l0, h1, l1;
                        split2(make_float2(a0[0], a0[1]), h0.x, l0.x);
                        split2(make_float2(a1[0], a1[1]), h0.y, l0.y);
                        split2(make_float2(a0[2], a0[3]), h1.x, l1.x);
                        split2(make_float2(a1[2], a1[3]), h1.y, l1.y);
                        g_KBh[s0] = h0; g_KBl[s0] = l0;
                        g_KBh[s1] = h1; g_KBl[s1] = l1;
                    }
                }
            }
        }
    }
}

// ===========================================================================
// Flash attention: Q frags in SMEM, 128 q-rows/CTA, 256 threads, 2 CTAs/SM.
// S: bf16 split-3. PV: fp16 P (single) x fp16 V hi/lo = 2 MMAs (exact cover).
// ===========================================================================
#define ASTAGE   32768
#define AQH_OFF  65536
#define AQL_OFF  81920
#define ATTN_SMEM 98304

__global__ __launch_bounds__(256, 2)
void attn_mma5()
{
    const int qt = 15 - blockIdx.x;   // heavy CTAs first
    const int h  = blockIdx.y;
    const int b  = blockIdx.z;
    const int BH = b * 16 + h;

    extern __shared__ char smem[];
    const uint32_t sb = smem_u32(smem);

    const int tid = threadIdx.x;
    const int la  = tid & 31;
    const int w   = tid >> 5;
    const int r_in  = la >> 2;
    const int cpair = (la & 3) * 2;
    const int qbase = qt * 128;
    const int row0  = qbase + w * 16 + r_in;
    const int row1  = row0 + 8;

    // --- issue Q fragments (one cp.async group, stays resident) ---
    {
        size_t qb = ((size_t)BH * 128 + qt * 8) * 128;   // uint4 units
#pragma unroll
        for (int rep = 0; rep < 4; rep++) {
            int u = rep * 256 + tid;                      // 0..1023
            CP16(sb + AQH_OFF + u * 16, g_QAh + qb + u);
            CP16(sb + AQL_OFF + u * 16, g_QAl + qb + u);
        }
        CP_COMMIT();
    }

    auto issue_tile = [&](int stage, int kt) {
        uint32_t base = sb + stage * ASTAGE;
        size_t t = ((size_t)BH * 32 + kt) * 512;
#pragma unroll
        for (int rep = 0; rep < 2; rep++) {
            int u = rep * 256 + tid;
            CP16(base + u * 16,         (const uint4*)g_KBh + t + u);
            CP16(base + 8192 + u * 16,  (const uint4*)g_KBl + t + u);
            CP16(base + 16384 + u * 16, (const uint4*)g_VBh + t + u);
            CP16(base + 24576 + u * 16, (const uint4*)g_VBl + t + u);
        }
        CP_COMMIT();
    };

    float o[8][4];
#pragma unroll
    for (int nf = 0; nf < 8; nf++)
#pragma unroll
        for (int r = 0; r < 4; r++) o[nf][r] = 0.f;
    float m0 = -1e30f, m1 = -1e30f, l0 = 0.f, l1 = 0.f;

    const int ntiles = 2 * qt + 2;
    issue_tile(0, 0);

    for (int kt = 0; kt < ntiles; kt++) {
        if (kt + 1 < ntiles) {
            issue_tile((kt + 1) & 1, kt + 1);
            CP_WAIT1();
        } else {
            CP_WAIT0();
        }
        __syncthreads();

        char* stg = smem + (kt & 1) * ASTAGE;
        const int kbase = kt * 64;

        if (kbase <= qbase + w * 16 + 15) {
            // --- S = Q K^T  (split-3; term-major passes per kf) ---
            float sfr[8][4];
#pragma unroll
            for (int nf = 0; nf < 8; nf++)
#pragma unroll
                for (int r = 0; r < 4; r++) sfr[nf][r] = 0.f;

#pragma unroll
            for (int kf = 0; kf < 4; kf++) {
                int qoff = ((w * 4 + kf) << 9) + (la << 4);
                uint4 qh = *(const uint4*)(smem + AQH_OFF + qoff);
                uint4 ql = *(const uint4*)(smem + AQL_OFF + qoff);
#pragma unroll
                for (int nf = 0; nf < 8; nf++) {
                    uint2 kh = *(const uint2*)(stg + ((nf * 4 + kf) << 8) + (la << 3));
                    mma16816(sfr[nf], qh, kh);
                }
#pragma unroll
                for (int nf = 0; nf < 8; nf++) {
                    uint2 kl = *(const uint2*)(stg + 8192 + ((nf * 4 + kf) << 8) + (la << 3));
                    mma16816(sfr[nf], qh, kl);
                }
#pragma unroll
                for (int nf = 0; nf < 8; nf++) {
                    uint2 kh = *(const uint2*)(stg + ((nf * 4 + kf) << 8) + (la << 3));
                    mma16816(sfr[nf], ql, kh);
                }
            }

            // --- causal mask (near-diagonal tiles only) ---
            if (kbase + 63 > qbase + w * 16) {
#pragma unroll
                for (int nf = 0; nf < 8; nf++) {
                    int c = kbase + nf * 8 + cpair;
                    if (c     > row0) sfr[nf][0] = -1e30f;
                    if (c + 1 > row0) sfr[nf][1] = -1e30f;
                    if (c     > row1) sfr[nf][2] = -1e30f;
                    if (c + 1 > row1) sfr[nf][3] = -1e30f;
                }
            }

            // --- online softmax (exp2 domain) ---
            float mx0 = -1e30f, mx1 = -1e30f;
#pragma unroll
            for (int nf = 0; nf < 8; nf++) {
                mx0 = fmaxf(mx0, fmaxf(sfr[nf][0], sfr[nf][1]));
                mx1 = fmaxf(mx1, fmaxf(sfr[nf][2], sfr[nf][3]));
            }
            mx0 = fmaxf(mx0, __shfl_xor_sync(0xffffffffu, mx0, 1));
            mx0 = fmaxf(mx0, __shfl_xor_sync(0xffffffffu, mx0, 2));
            mx1 = fmaxf(mx1, __shfl_xor_sync(0xffffffffu, mx1, 1));
            mx1 = fmaxf(mx1, __shfl_xor_sync(0xffffffffu, mx1, 2));

            float mn0 = fmaxf(m0, mx0), mn1 = fmaxf(m1, mx1);
            float a0 = ex2(m0 - mn0), a1 = ex2(m1 - mn1);
            float s0 = 0.f, s1 = 0.f;
#pragma unroll
            for (int nf = 0; nf < 8; nf++) {
                sfr[nf][0] = ex2(sfr[nf][0] - mn0);
                sfr[nf][1] = ex2(sfr[nf][1] - mn0);
                sfr[nf][2] = ex2(sfr[nf][2] - mn1);
                sfr[nf][3] = ex2(sfr[nf][3] - mn1);
                s0 += sfr[nf][0] + sfr[nf][1];
                s1 += sfr[nf][2] + sfr[nf][3];
            }
            s0 += __shfl_xor_sync(0xffffffffu, s0, 1);
            s0 += __shfl_xor_sync(0xffffffffu, s0, 2);
            s1 += __shfl_xor_sync(0xffffffffu, s1, 1);
            s1 += __shfl_xor_sync(0xffffffffu, s1, 2);

            l0 = l0 * a0 + s0;  l1 = l1 * a1 + s1;
            m0 = mn0;           m1 = mn1;
#pragma unroll
            for (int nf = 0; nf < 8; nf++) {
                o[nf][0] *= a0; o[nf][1] *= a0;
                o[nf][2] *= a1; o[nf][3] *= a1;
            }

            // --- O += P V  (P fp16 single, V fp16 hi/lo: 2 MMAs, exact cover) ---
#pragma unroll
            for (int kf2 = 0; kf2 < 4; kf2++) {
                uint4 Ph;
                Ph.x = packh2(sfr[2 * kf2][0],     sfr[2 * kf2][1]);
                Ph.y = packh2(sfr[2 * kf2][2],     sfr[2 * kf2][3]);
                Ph.z = packh2(sfr[2 * kf2 + 1][0], sfr[2 * kf2 + 1][1]);
                Ph.w = packh2(sfr[2 * kf2 + 1][2], sfr[2 * kf2 + 1][3]);
#pragma unroll
                for (int nf = 0; nf < 8; nf++) {
                    uint2 vh = *(const uint2*)(stg + 16384 + ((nf * 4 + kf2) << 8) + (la << 3));
                    mma16816h(o[nf], Ph, vh);
                }
#pragma unroll
                for (int nf = 0; nf < 8; nf++) {
                    uint2 vl = *(const uint2*)(stg + 24576 + ((nf * 4 + kf2) << 8) + (la << 3));
                    mma16816h(o[nf], Ph, vl);
                }
            }
        }
        __syncthreads();
    }

    // --- epilogue: write gemm2 A-frag planes directly (o / l) ---
    float i0 = 1.f / l0, i1 = 1.f / l1;
    const int r16 = b * 128 + qt * 8 + w;
#pragma unroll
    for (int nf = 0; nf < 8; nf += 2) {
        int kfg = h * 4 + (nf >> 1);
        size_t slot = ((size_t)r16 * 64 + kfg) * 32 + la;
        uint4 ah4, al4;
        split2(make_float2(o[nf][0] * i0,     o[nf][1] * i0),     ah4.x, al4.x);
        split2(make_float2(o[nf][2] * i1,     o[nf][3] * i1),     ah4.y, al4.y);
        split2(make_float2(o[nf + 1][0] * i0, o[nf + 1][1] * i0), ah4.z, al4.z);
        split2(make_float2(o[nf + 1][2] * i1, o[nf + 1][3] * i1), ah4.w, al4.w);
        g_atAh[slot] = ah4;
        g_atAl[slot] = al4;
    }
}

// ---------------------------------------------------------------------------
// Launch
// ---------------------------------------------------------------------------
extern "C" void kernel_launch(void* const* d_in, const int* in_sizes, int n_in,
                              void* d_out, int out_size)
{
    const float* x = nullptr, *Wkqv = nullptr, *Wproj = nullptr, *bproj = nullptr;
    for (int i = 0; i < n_in; i++) {
        int sz = in_sizes[i];
        if      (sz == TB * TT * NE)      x     = (const float*)d_in[i];
        else if (sz == 3 * NE * NE)       Wkqv  = (const float*)d_in[i];
        else if (sz == NE * NE)           Wproj = (const float*)d_in[i];
        else if (sz == NE)                bproj = (const float*)d_in[i];
    }
    float* out = (float*)d_out;

    uint4 *xAh, *xAl, *atAh, *atAl;
    uint2 *WkBh, *WkBl, *WpBh, *WpBl;
    cudaGetSymbolAddress((void**)&xAh,  g_xAh);
    cudaGetSymbolAddress((void**)&xAl,  g_xAl);
    cudaGetSymbolAddress((void**)&atAh, g_atAh);
    cudaGetSymbolAddress((void**)&atAl, g_atAl);
    cudaGetSymbolAddress((void**)&WkBh, g_WkBh);
    cudaGetSymbolAddress((void**)&WkBl, g_WkBl);
    cudaGetSymbolAddress((void**)&WpBh, g_WpBh);
    cudaGetSymbolAddress((void**)&WpBl, g_WpBl);

    cudaFuncSetAttribute(gemm_bf,
                         cudaFuncAttributeMaxDynamicSharedMemorySize, GSMEM);
    cudaFuncSetAttribute(attn_mma5,
                         cudaFuncAttributeMaxDynamicSharedMemorySize, ATTN_SMEM);

    // Prep inputs: fragment-major bf16 hi/lo (single launch)
    prep_all<<<6144, 256>>>(x, Wkqv, Wproj);

    // 1) KQV projection, fused epilogue -> Q/K (bf16) + V (fp16) frag planes
    {
        dim3 grid(C3 / 128, 32);
        gemm_bf<<<grid, 128, GSMEM>>>(xAh, xAl, WkBh, WkBl, nullptr, out, NE, 1);
    }

    // 2) Causal flash attention -> g_atA planes
    {
        dim3 grid(TT / 128, NH, TB);
        attn_mma5<<<grid, 256, ATTN_SMEM>>>();
    }

    // 3) Output projection + bias
    {
        dim3 grid(NE / 128, 32);
        gemm_bf<<<grid, 128, GSMEM>>>(atAh, atAl, WpBh, WpBl, bproj, out, NE, 0);
    }
}

// round 16
// speedup vs baseline: 1.2272x; 1.0804x over previous
#include <cuda_runtime.h>
#include <cuda_bf16.h>
#include <cuda_fp16.h>
#include <math.h>
#include <stddef.h>
#include <stdint.h>

// Problem constants
#define TB 2
#define TT 2048
#define NE 1024
#define NH 16
#define HD 64
#define C3 (3 * NE)   // 3072

// Q scale: 1/sqrt(64) * log2(e)  (softmax runs in exp2 domain)
#define QSCALE 0.18033688011112042f

// Fragment-major bf16 hi/lo planes (mma register layout in gmem).
__device__ uint4 g_xAh [(size_t)256 * 64 * 32];   // x      A-frags
__device__ uint4 g_xAl [(size_t)256 * 64 * 32];
__device__ uint4 g_atAh[(size_t)256 * 64 * 32];   // attn out A-frags (gemm2 input)
__device__ uint4 g_atAl[(size_t)256 * 64 * 32];
__device__ uint2 g_WkBh[(size_t)384 * 64 * 32];   // W_kqv  B-frags
__device__ uint2 g_WkBl[(size_t)384 * 64 * 32];
__device__ uint2 g_WpBh[(size_t)128 * 64 * 32];   // W_proj B-frags
__device__ uint2 g_WpBl[(size_t)128 * 64 * 32];

// Attention planes, per (b,h):
__device__ uint4 g_QAh[(size_t)32 * 128 * 4 * 32];   // fp16 hi/lo (QSCALE folded)
__device__ uint4 g_QAl[(size_t)32 * 128 * 4 * 32];
__device__ uint2 g_KBh[(size_t)32 * 32 * 8 * 4 * 32]; // fp16 single
__device__ uint2 g_VBh[(size_t)32 * 32 * 8 * 4 * 32]; // fp16 hi/lo
__device__ uint2 g_VBl[(size_t)32 * 32 * 8 * 4 * 32];

// ===========================================================================
// PTX helpers
// ===========================================================================
static __device__ __forceinline__ void mma16816(float* d, const uint4& a, const uint2& b) {
    asm volatile(
        "mma.sync.aligned.m16n8k16.row.col.f32.bf16.bf16.f32 "
        "{%0,%1,%2,%3}, {%4,%5,%6,%7}, {%8,%9}, {%0,%1,%2,%3};"
        : "+f"(d[0]), "+f"(d[1]), "+f"(d[2]), "+f"(d[3])
        : "r"(a.x), "r"(a.y), "r"(a.z), "r"(a.w), "r"(b.x), "r"(b.y));
}

// fp16 variant
static __device__ __forceinline__ void mma16816h(float* d, const uint4& a, const uint2& b) {
    asm volatile(
        "mma.sync.aligned.m16n8k16.row.col.f32.f16.f16.f32 "
        "{%0,%1,%2,%3}, {%4,%5,%6,%7}, {%8,%9}, {%0,%1,%2,%3};"
        : "+f"(d[0]), "+f"(d[1]), "+f"(d[2]), "+f"(d[3])
        : "r"(a.x), "r"(a.y), "r"(a.z), "r"(a.w), "r"(b.x), "r"(b.y));
}

static __device__ __forceinline__ void split2(float2 f, uint32_t& h, uint32_t& l) {
    __nv_bfloat162 hp = __floats2bfloat162_rn(f.x, f.y);
    float2 hf = __bfloat1622float2(hp);
    __nv_bfloat162 lp = __floats2bfloat162_rn(f.x - hf.x, f.y - hf.y);
    h = *reinterpret_cast<uint32_t*>(&hp);
    l = *reinterpret_cast<uint32_t*>(&lp);
}

// fp16 hi/lo split
static __device__ __forceinline__ void hsplit2(float2 f, uint32_t& h, uint32_t& l) {
    __half2 hp = __floats2half2_rn(f.x, f.y);
    float2 hf = __half22float2(hp);
    __half2 lp = __floats2half2_rn(f.x - hf.x, f.y - hf.y);
    h = *reinterpret_cast<uint32_t*>(&hp);
    l = *reinterpret_cast<uint32_t*>(&lp);
}

static __device__ __forceinline__ uint32_t packh2(float a, float b) {
    __half2 p = __floats2half2_rn(a, b);
    return *reinterpret_cast<uint32_t*>(&p);
}

static __device__ __forceinline__ float ex2(float x) {
    float r;
    asm("ex2.approx.f32 %0, %1;" : "=f"(r) : "f"(x));
    return r;
}

static __device__ __forceinline__ uint32_t smem_u32(const void* p) {
    uint32_t a;
    asm("{ .reg .u64 t; cvta.to.shared.u64 t, %1; cvt.u32.u64 %0, t; }"
        : "=r"(a) : "l"(p));
    return a;
}

#define CP16(dst, src) \
    asm volatile("cp.async.cg.shared.global [%0], [%1], 16;" :: "r"(dst), "l"(src))
#define CP_COMMIT() asm volatile("cp.async.commit_group;" ::: "memory")
#define CP_WAIT2()  asm volatile("cp.async.wait_group 2;" ::: "memory")
#define CP_WAIT1()  asm volatile("cp.async.wait_group 1;" ::: "memory")
#define CP_WAIT0()  asm volatile("cp.async.wait_group 0;" ::: "memory")

// ===========================================================================
// Merged prep kernel
// ===========================================================================
__global__ __launch_bounds__(256)
void prep_all(const float* __restrict__ x, const float* __restrict__ Wk,
              const float* __restrict__ Wp)
{
    int blk = blockIdx.x;
    if (blk < 2048) {
        int slot = blk * 256 + threadIdx.x;
        int frag = slot >> 5, la = slot & 31;
        int row = ((frag >> 6) << 4) + (la >> 2);
        int k   = ((frag & 63) << 4) + ((la & 3) << 1);
        const float* p = x + (size_t)row * 1024 + k;
        float2 x0 = *(const float2*)p;
        float2 x1 = *(const float2*)(p + 8 * 1024);
        float2 x2 = *(const float2*)(p + 8);
        float2 x3 = *(const float2*)(p + 8 * 1024 + 8);
        uint4 h, l;
        split2(x0, h.x, l.x);
        split2(x1, h.y, l.y);
        split2(x2, h.z, l.z);
        split2(x3, h.w, l.w);
        g_xAh[slot] = h;
        g_xAl[slot] = l;
    } else {
        const float* src;
        uint2 *hi, *lo;
        int slot;
        if (blk < 5120) {
            slot = (blk - 2048) * 256 + threadIdx.x;
            src = Wk; hi = g_WkBh; lo = g_WkBl;
        } else {
            slot = (blk - 5120) * 256 + threadIdx.x;
            src = Wp; hi = g_WpBh; lo = g_WpBl;
        }
        int frag = slot >> 5, la = slot & 31;
        int n = ((frag >> 6) << 3) + (la >> 2);
        int k = ((frag & 63) << 4) + ((la & 3) << 1);
        const float* p = src + (size_t)n * 1024 + k;
        float2 x0 = *(const float2*)p;
        float2 x1 = *(const float2*)(p + 8);
        uint2 h, l;
        split2(x0, h.x, l.x);
        split2(x1, h.y, l.y);
        hi[slot] = h;
        lo[slot] = l;
    }
}

// ===========================================================================
// GEMM via mma.sync, warp tile 64x64, 4 warps (2x2), 2 CTAs/SM.
// ===========================================================================
#define GSTAGE 32768
#define GSMEM  (3 * GSTAGE)

__global__ __launch_bounds__(128, 2)
void gemm_bf(const uint4* __restrict__ Ah, const uint4* __restrict__ Al,
             const uint2* __restrict__ Bh, const uint2* __restrict__ Bl,
             const float* __restrict__ bias, float* __restrict__ Cout,
             int N, int mode)
{
    extern __shared__ char smem[];
    const uint32_t sb = smem_u32(smem);
    const int tid = threadIdx.x;
    const int la  = tid & 31;
    const int wrp = tid >> 5;   // 0..3
    const int wm  = wrp >> 1;   // 0..1
    const int wn  = wrp & 1;    // 0..1
    const int r16b = blockIdx.y * 8;
    const int n8b  = blockIdx.x * 16;

    float acc[4][8][4];
#pragma unroll
    for (int i = 0; i < 4; i++)
#pragma unroll
        for (int j = 0; j < 8; j++)
#pragma unroll
            for (int r = 0; r < 4; r++) acc[i][j][r] = 0.f;

    auto issue = [&](int stage, int kc) {
        uint32_t base = sb + stage * GSTAGE;
#pragma unroll
        for (int rep = 0; rep < 4; rep++) {
            int u = rep * 128 + tid;           // 0..511
            int f = u >> 5, ln = u & 31;
            int ga = ((r16b + (f >> 1)) << 6) + (kc << 1) + (f & 1);
            CP16(base + f * 512 + ln * 16,        Ah + (size_t)ga * 32 + ln);
            CP16(base + 8192 + f * 512 + ln * 16, Al + (size_t)ga * 32 + ln);
        }
#pragma unroll
        for (int rep = 0; rep < 4; rep++) {
            int u = rep * 128 + tid;           // 0..511
            int f = u >> 4, j = u & 15;
            int gb = ((n8b + (f >> 1)) << 6) + (kc << 1) + (f & 1);
            CP16(base + 16384 + f * 256 + j * 16,
                 (const uint4*)Bh + (size_t)gb * 16 + j);
            CP16(base + 24576 + f * 256 + j * 16,
                 (const uint4*)Bl + (size_t)gb * 16 + j);
        }
        CP_COMMIT();
    };

    auto compute = [&](int stage) {
        char* base = smem + stage * GSTAGE;
#pragma unroll
        for (int kf = 0; kf < 2; kf++) {
            uint4 ah[4], al[4];
#pragma unroll
            for (int i = 0; i < 4; i++) {
                int foff = ((wm * 4 + i) * 2 + kf) * 512 + la * 16;
                ah[i] = *(const uint4*)(base + foff);
                al[i] = *(const uint4*)(base + 8192 + foff);
            }
#pragma unroll
            for (int jg = 0; jg < 2; jg++) {
                uint2 bh[4], bl[4];
#pragma unroll
                for (int jj = 0; jj < 4; jj++) {
                    int boff = ((wn * 8 + jg * 4 + jj) * 2 + kf) * 256 + la * 8;
                    bh[jj] = *(const uint2*)(base + 16384 + boff);
                    bl[jj] = *(const uint2*)(base + 24576 + boff);
                }
#pragma unroll
                for (int i = 0; i < 4; i++)
#pragma unroll
                    for (int jj = 0; jj < 4; jj++)
                        mma16816(acc[i][jg * 4 + jj], ah[i], bh[jj]);
#pragma unroll
                for (int i = 0; i < 4; i++)
#pragma unroll
                    for (int jj = 0; jj < 4; jj++)
                        mma16816(acc[i][jg * 4 + jj], ah[i], bl[jj]);
#pragma unroll
                for (int i = 0; i < 4; i++)
#pragma unroll
                    for (int jj = 0; jj < 4; jj++)
                        mma16816(acc[i][jg * 4 + jj], al[i], bh[jj]);
            }
        }
    };

    issue(0, 0);
    issue(1, 1);

    for (int kc = 0; kc < 32; kc++) {
        if (kc + 2 < 32) {
            issue((kc + 2) % 3, kc + 2);
            CP_WAIT2();
        } else if (kc + 1 < 32) {
            CP_WAIT1();
        } else {
            CP_WAIT0();
        }
        __syncthreads();
        compute(kc % 3);
        __syncthreads();
    }

    const int brow = blockIdx.y * 128;
    const int bcol = blockIdx.x * 128;

    if (mode == 0) {
        // plain fp32 epilogue (+bias)
#pragma unroll
        for (int j = 0; j < 8; j++) {
            int c0 = bcol + wn * 64 + j * 8 + (la & 3) * 2;
            float bx = 0.f, by = 0.f;
            if (bias) { bx = bias[c0]; by = bias[c0 + 1]; }
#pragma unroll
            for (int i = 0; i < 4; i++) {
                int r0 = brow + wm * 64 + i * 16 + (la >> 2);
                float2 o0, o1;
                o0.x = acc[i][j][0] + bx; o0.y = acc[i][j][1] + by;
                o1.x = acc[i][j][2] + bx; o1.y = acc[i][j][3] + by;
                *(float2*)&Cout[(size_t)r0 * N + c0]       = o0;
                *(float2*)&Cout[(size_t)(r0 + 8) * N + c0] = o1;
            }
        }
    } else {
        // fused kqv epilogue. cols [0,1024)=k, [1024,2048)=q, [2048,3072)=v
        int role = bcol >> 10;
        if (role == 2) {
            // V: stage acc fp32 to smem, transpose, write fp16 V B-frag planes.
            float* VS = (float*)smem;   // [128][132] floats
#pragma unroll
            for (int j = 0; j < 8; j++) {
                int c0 = wn * 64 + j * 8 + (la & 3) * 2;
#pragma unroll
                for (int i = 0; i < 4; i++) {
                    int r0 = wm * 64 + i * 16 + (la >> 2);
                    VS[r0 * 132 + c0]           = acc[i][j][0];
                    VS[r0 * 132 + c0 + 1]       = acc[i][j][1];
                    VS[(r0 + 8) * 132 + c0]     = acc[i][j][2];
                    VS[(r0 + 8) * 132 + c0 + 1] = acc[i][j][3];
                }
            }
            __syncthreads();
            int b     = brow >> 11;
            int trow  = brow & 2047;
            int hbase = (bcol - 2048) >> 6;
#pragma unroll
            for (int it = 0; it < 32; it++) {
                int f   = it * 4 + wrp;          // 0..127 local frag
                int kf2 = f & 3;
                int nf  = (f >> 2) & 7;
                int ktl = (f >> 5) & 1;
                int hh  = f >> 6;
                int dl  = hh * 64 + nf * 8 + (la >> 2);
                int kl  = ktl * 64 + kf2 * 16 + (la & 3) * 2;
                float v00 = VS[kl * 132 + dl];
                float v01 = VS[(kl + 1) * 132 + dl];
                float v10 = VS[(kl + 8) * 132 + dl];
                float v11 = VS[(kl + 9) * 132 + dl];
                uint2 vh, vl;
                hsplit2(make_float2(v00, v01), vh.x, vl.x);
                hsplit2(make_float2(v10, v11), vh.y, vl.y);
                int BH = b * 16 + hbase + hh;
                int kt = (trow >> 6) + ktl;
                size_t slot = (size_t)(BH * 32 + kt) * 1024 + (nf * 4 + kf2) * 32 + la;
                g_VBh[slot] = vh;
                g_VBl[slot] = vl;
            }
        } else {
#pragma unroll
            for (int t = 0; t < 4; t++) {
                int gcol = (bcol & 1023) + wn * 64 + t * 16;
                int h  = gcol >> 6;
                int kf = (gcol >> 4) & 3;
#pragma unroll
                for (int i = 0; i < 4; i++) {
                    int grow = brow + wm * 64 + i * 16;
                    int b = grow >> 11, trow = grow & 2047;
                    int BH = b * 16 + h;
                    const float* a0 = acc[i][2 * t];
                    const float* a1 = acc[i][2 * t + 1];
                    if (role == 1) {
                        // Q A-frag: fp16 hi/lo, scale QSCALE
                        size_t slot = ((((size_t)BH * 128) + (trow >> 4)) * 4 + kf) * 32 + la;
                        uint4 ah4, al4;
                        hsplit2(make_float2(a0[0] * QSCALE, a0[1] * QSCALE), ah4.x, al4.x);
                        hsplit2(make_float2(a0[2] * QSCALE, a0[3] * QSCALE), ah4.y, al4.y);
                        hsplit2(make_float2(a1[0] * QSCALE, a1[1] * QSCALE), ah4.z, al4.z);
                        hsplit2(make_float2(a1[2] * QSCALE, a1[3] * QSCALE), ah4.w, al4.w);
                        g_QAh[slot] = ah4;
                        g_QAl[slot] = al4;
                    } else {
                        // K B-frags: single fp16
                        int kt = trow >> 6;
                        size_t fb = ((size_t)BH * 32 + kt) * 8;
                        size_t s0 = ((fb + 2 * i)     * 4 + kf) * 32 + la;
                        size_t s1 = ((fb + 2 * i + 1) * 4 + kf) * 32 + la;
                        uint2 h0, h1;
                        h0.x = packh2(a0[0], a0[1]);
                        h0.y = packh2(a1[0], a1[1]);
                        h1.x = packh2(a0[2], a0[3]);
                        h1.y = packh2(a1[2], a1[3]);
                        g_KBh[s0] = h0;
                        g_KBh[s1] = h1;
                    }
                }
            }
        }
    }
}

// ===========================================================================
// Flash attention: Q frags (fp16 hi/lo) in SMEM, 128 q-rows/CTA, 256 threads,
// 2 CTAs/SM. S: fp16 Qh/Ql x K = 2 MMAs. PV: fp16 P x V hi/lo = 2 MMAs.
// Stage (24KB): KH [0,8K) | VH [8K,16K) | VL [16K,24K). 2 stages + Q 32KB.
// ===========================================================================
#define ASTAGE   24576
#define AQH_OFF  49152
#define AQL_OFF  65536
#define ATTN_SMEM 81920

__global__ __launch_bounds__(256, 2)
void attn_mma5()
{
    const int qt = 15 - blockIdx.x;   // heavy CTAs first
    const int h  = blockIdx.y;
    const int b  = blockIdx.z;
    const int BH = b * 16 + h;

    extern __shared__ char smem[];
    const uint32_t sb = smem_u32(smem);

    const int tid = threadIdx.x;
    const int la  = tid & 31;
    const int w   = tid >> 5;
    const int r_in  = la >> 2;
    const int cpair = (la & 3) * 2;
    const int qbase = qt * 128;
    const int row0  = qbase + w * 16 + r_in;
    const int row1  = row0 + 8;

    // --- issue Q fragments (one cp.async group, stays resident) ---
    {
        size_t qb = ((size_t)BH * 128 + qt * 8) * 128;   // uint4 units
#pragma unroll
        for (int rep = 0; rep < 4; rep++) {
            int u = rep * 256 + tid;                      // 0..1023
            CP16(sb + AQH_OFF + u * 16, g_QAh + qb + u);
            CP16(sb + AQL_OFF + u * 16, g_QAl + qb + u);
        }
        CP_COMMIT();
    }

    auto issue_tile = [&](int stage, int kt) {
        uint32_t base = sb + stage * ASTAGE;
        size_t t = ((size_t)BH * 32 + kt) * 512;
#pragma unroll
        for (int rep = 0; rep < 2; rep++) {
            int u = rep * 256 + tid;   // 0..511
            CP16(base + u * 16,         (const uint4*)g_KBh + t + u);
            CP16(base + 8192 + u * 16,  (const uint4*)g_VBh + t + u);
            CP16(base + 16384 + u * 16, (const uint4*)g_VBl + t + u);
        }
        CP_COMMIT();
    };

    float o[8][4];
#pragma unroll
    for (int nf = 0; nf < 8; nf++)
#pragma unroll
        for (int r = 0; r < 4; r++) o[nf][r] = 0.f;
    float m0 = -1e30f, m1 = -1e30f, l0 = 0.f, l1 = 0.f;

    const int ntiles = 2 * qt + 2;
    issue_tile(0, 0);

    for (int kt = 0; kt < ntiles; kt++) {
        if (kt + 1 < ntiles) {
            issue_tile((kt + 1) & 1, kt + 1);
            CP_WAIT1();
        } else {
            CP_WAIT0();
        }
        __syncthreads();

        char* stg = smem + (kt & 1) * ASTAGE;
        const int kbase = kt * 64;

        if (kbase <= qbase + w * 16 + 15) {
            // --- S = Q K^T  (fp16: Qh pass + Ql pass) ---
            float sfr[8][4];
#pragma unroll
            for (int nf = 0; nf < 8; nf++)
#pragma unroll
                for (int r = 0; r < 4; r++) sfr[nf][r] = 0.f;

#pragma unroll
            for (int kf = 0; kf < 4; kf++) {
                int qoff = ((w * 4 + kf) << 9) + (la << 4);
                uint4 qh = *(const uint4*)(smem + AQH_OFF + qoff);
                uint4 ql = *(const uint4*)(smem + AQL_OFF + qoff);
#pragma unroll
                for (int nf = 0; nf < 8; nf++) {
                    uint2 kh = *(const uint2*)(stg + ((nf * 4 + kf) << 8) + (la << 3));
                    mma16816h(sfr[nf], qh, kh);
                }
#pragma unroll
                for (int nf = 0; nf < 8; nf++) {
                    uint2 kh = *(const uint2*)(stg + ((nf * 4 + kf) << 8) + (la << 3));
                    mma16816h(sfr[nf], ql, kh);
                }
            }

            // --- causal mask (near-diagonal tiles only) ---
            if (kbase + 63 > qbase + w * 16) {
#pragma unroll
                for (int nf = 0; nf < 8; nf++) {
                    int c = kbase + nf * 8 + cpair;
                    if (c     > row0) sfr[nf][0] = -1e30f;
                    if (c + 1 > row0) sfr[nf][1] = -1e30f;
                    if (c     > row1) sfr[nf][2] = -1e30f;
                    if (c + 1 > row1) sfr[nf][3] = -1e30f;
                }
            }

            // --- online softmax (exp2 domain) ---
            float mx0 = -1e30f, mx1 = -1e30f;
#pragma unroll
            for (int nf = 0; nf < 8; nf++) {
                mx0 = fmaxf(mx0, fmaxf(sfr[nf][0], sfr[nf][1]));
                mx1 = fmaxf(mx1, fmaxf(sfr[nf][2], sfr[nf][3]));
            }
            mx0 = fmaxf(mx0, __shfl_xor_sync(0xffffffffu, mx0, 1));
            mx0 = fmaxf(mx0, __shfl_xor_sync(0xffffffffu, mx0, 2));
            mx1 = fmaxf(mx1, __shfl_xor_sync(0xffffffffu, mx1, 1));
            mx1 = fmaxf(mx1, __shfl_xor_sync(0xffffffffu, mx1, 2));

            float mn0 = fmaxf(m0, mx0), mn1 = fmaxf(m1, mx1);
            float a0 = ex2(m0 - mn0), a1 = ex2(m1 - mn1);
            float s0 = 0.f, s1 = 0.f;
#pragma unroll
            for (int nf = 0; nf < 8; nf++) {
                sfr[nf][0] = ex2(sfr[nf][0] - mn0);
                sfr[nf][1] = ex2(sfr[nf][1] - mn0);
                sfr[nf][2] = ex2(sfr[nf][2] - mn1);
                sfr[nf][3] = ex2(sfr[nf][3] - mn1);
                s0 += sfr[nf][0] + sfr[nf][1];
                s1 += sfr[nf][2] + sfr[nf][3];
            }
            s0 += __shfl_xor_sync(0xffffffffu, s0, 1);
            s0 += __shfl_xor_sync(0xffffffffu, s0, 2);
            s1 += __shfl_xor_sync(0xffffffffu, s1, 1);
            s1 += __shfl_xor_sync(0xffffffffu, s1, 2);

            l0 = l0 * a0 + s0;  l1 = l1 * a1 + s1;
            m0 = mn0;           m1 = mn1;
#pragma unroll
            for (int nf = 0; nf < 8; nf++) {
                o[nf][0] *= a0; o[nf][1] *= a0;
                o[nf][2] *= a1; o[nf][3] *= a1;
            }

            // --- O += P V  (P fp16, V fp16 hi/lo: 2 MMAs) ---
#pragma unroll
            for (int kf2 = 0; kf2 < 4; kf2++) {
                uint4 Ph;
                Ph.x = packh2(sfr[2 * kf2][0],     sfr[2 * kf2][1]);
                Ph.y = packh2(sfr[2 * kf2][2],     sfr[2 * kf2][3]);
                Ph.z = packh2(sfr[2 * kf2 + 1][0], sfr[2 * kf2 + 1][1]);
                Ph.w = packh2(sfr[2 * kf2 + 1][2], sfr[2 * kf2 + 1][3]);
#pragma unroll
                for (int nf = 0; nf < 8; nf++) {
                    uint2 vh = *(const uint2*)(stg + 8192 + ((nf * 4 + kf2) << 8) + (la << 3));
                    mma16816h(o[nf], Ph, vh);
                }
#pragma unroll
                for (int nf = 0; nf < 8; nf++) {
                    uint2 vl = *(const uint2*)(stg + 16384 + ((nf * 4 + kf2) << 8) + (la << 3));
                    mma16816h(o[nf], Ph, vl);
                }
            }
        }
        __syncthreads();
    }

    // --- epilogue: write gemm2 A-frag planes directly (o / l) ---
    float i0 = 1.f / l0, i1 = 1.f / l1;
    const int r16 = b * 128 + qt * 8 + w;
#pragma unroll
    for (int nf = 0; nf < 8; nf += 2) {
        int kfg = h * 4 + (nf >> 1);
        size_t slot = ((size_t)r16 * 64 + kfg) * 32 + la;
        uint4 ah4, al4;
        split2(make_float2(o[nf][0] * i0,     o[nf][1] * i0),     ah4.x, al4.x);
        split2(make_float2(o[nf][2] * i1,     o[nf][3] * i1),     ah4.y, al4.y);
        split2(make_float2(o[nf + 1][0] * i0, o[nf + 1][1] * i0), ah4.z, al4.z);
        split2(make_float2(o[nf + 1][2] * i1, o[nf + 1][3] * i1), ah4.w, al4.w);
        g_atAh[slot] = ah4;
        g_atAl[slot] = al4;
    }
}

// ---------------------------------------------------------------------------
// Launch
// ---------------------------------------------------------------------------
extern "C" void kernel_launch(void* const* d_in, const int* in_sizes, int n_in,
                              void* d_out, int out_size)
{
    const float* x = nullptr, *Wkqv = nullptr, *Wproj = nullptr, *bproj = nullptr;
    for (int i = 0; i < n_in; i++) {
        int sz = in_sizes[i];
        if      (sz == TB * TT * NE)      x     = (const float*)d_in[i];
        else if (sz == 3 * NE * NE)       Wkqv  = (const float*)d_in[i];
        else if (sz == NE * NE)           Wproj = (const float*)d_in[i];
        else if (sz == NE)                bproj = (const float*)d_in[i];
    }
    float* out = (float*)d_out;

    uint4 *xAh, *xAl, *atAh, *atAl;
    uint2 *WkBh, *WkBl, *WpBh, *WpBl;
    cudaGetSymbolAddress((void**)&xAh,  g_xAh);
    cudaGetSymbolAddress((void**)&xAl,  g_xAl);
    cudaGetSymbolAddress((void**)&atAh, g_atAh);
    cudaGetSymbolAddress((void**)&atAl, g_atAl);
    cudaGetSymbolAddress((void**)&WkBh, g_WkBh);
    cudaGetSymbolAddress((void**)&WkBl, g_WkBl);
    cudaGetSymbolAddress((void**)&WpBh, g_WpBh);
    cudaGetSymbolAddress((void**)&WpBl, g_WpBl);

    cudaFuncSetAttribute(gemm_bf,
                         cudaFuncAttributeMaxDynamicSharedMemorySize, GSMEM);
    cudaFuncSetAttribute(attn_mma5,
                         cudaFuncAttributeMaxDynamicSharedMemorySize, ATTN_SMEM);

    // Prep inputs: fragment-major bf16 hi/lo (single launch)
    prep_all<<<6144, 256>>>(x, Wkqv, Wproj);

    // 1) KQV projection, fused epilogue -> Q/K/V fp16 frag planes
    {
        dim3 grid(C3 / 128, 32);
        gemm_bf<<<grid, 128, GSMEM>>>(xAh, xAl, WkBh, WkBl, nullptr, out, NE, 1);
    }

    // 2) Causal flash attention -> g_atA planes
    {
        dim3 grid(TT / 128, NH, TB);
        attn_mma5<<<grid, 256, ATTN_SMEM>>>();
    }

    // 3) Output projection + bias
    {
        dim3 grid(NE / 128, 32);
        gemm_bf<<<grid, 128, GSMEM>>>(atAh, atAl, WpBh, WpBl, bproj, out, NE, 0);
    }
}

// round 17
// speedup vs baseline: 1.4509x; 1.1822x over previous
#include <cuda_runtime.h>
#include <cuda_bf16.h>
#include <cuda_fp16.h>
#include <math.h>
#include <stddef.h>
#include <stdint.h>

// Problem constants
#define TB 2
#define TT 2048
#define NE 1024
#define NH 16
#define HD 64
#define C3 (3 * NE)   // 3072

// Q scale: 1/sqrt(64) * log2(e)  (softmax runs in exp2 domain)
#define QSCALE 0.18033688011112042f

// Fragment-major fp16 planes (mma register layout in gmem).
__device__ uint4 g_xAh [(size_t)256 * 64 * 32];   // x      A-frags fp16 hi/lo
__device__ uint4 g_xAl [(size_t)256 * 64 * 32];
__device__ uint4 g_atAh[(size_t)256 * 64 * 32];   // attn out A-frags fp16 hi/lo
__device__ uint4 g_atAl[(size_t)256 * 64 * 32];
__device__ uint2 g_WkBh[(size_t)384 * 64 * 32];   // W_kqv  B-frags fp16 single
__device__ uint2 g_WpBh[(size_t)128 * 64 * 32];   // W_proj B-frags fp16 single

// Attention planes, per (b,h):
__device__ uint4 g_QAh[(size_t)32 * 128 * 4 * 32];   // fp16 hi/lo (QSCALE folded)
__device__ uint4 g_QAl[(size_t)32 * 128 * 4 * 32];
__device__ uint2 g_KBh[(size_t)32 * 32 * 8 * 4 * 32]; // fp16 single
__device__ uint2 g_VBh[(size_t)32 * 32 * 8 * 4 * 32]; // fp16 hi/lo
__device__ uint2 g_VBl[(size_t)32 * 32 * 8 * 4 * 32];

// ===========================================================================
// PTX helpers
// ===========================================================================
static __device__ __forceinline__ void mma16816h(float* d, const uint4& a, const uint2& b) {
    asm volatile(
        "mma.sync.aligned.m16n8k16.row.col.f32.f16.f16.f32 "
        "{%0,%1,%2,%3}, {%4,%5,%6,%7}, {%8,%9}, {%0,%1,%2,%3};"
        : "+f"(d[0]), "+f"(d[1]), "+f"(d[2]), "+f"(d[3])
        : "r"(a.x), "r"(a.y), "r"(a.z), "r"(a.w), "r"(b.x), "r"(b.y));
}

// fp16 hi/lo split
static __device__ __forceinline__ void hsplit2(float2 f, uint32_t& h, uint32_t& l) {
    __half2 hp = __floats2half2_rn(f.x, f.y);
    float2 hf = __half22float2(hp);
    __half2 lp = __floats2half2_rn(f.x - hf.x, f.y - hf.y);
    h = *reinterpret_cast<uint32_t*>(&hp);
    l = *reinterpret_cast<uint32_t*>(&lp);
}

static __device__ __forceinline__ uint32_t packh2(float a, float b) {
    __half2 p = __floats2half2_rn(a, b);
    return *reinterpret_cast<uint32_t*>(&p);
}

static __device__ __forceinline__ float ex2(float x) {
    float r;
    asm("ex2.approx.f32 %0, %1;" : "=f"(r) : "f"(x));
    return r;
}

static __device__ __forceinline__ uint32_t smem_u32(const void* p) {
    uint32_t a;
    asm("{ .reg .u64 t; cvta.to.shared.u64 t, %1; cvt.u32.u64 %0, t; }"
        : "=r"(a) : "l"(p));
    return a;
}

#define CP16(dst, src) \
    asm volatile("cp.async.cg.shared.global [%0], [%1], 16;" :: "r"(dst), "l"(src))
#define CP_COMMIT() asm volatile("cp.async.commit_group;" ::: "memory")
#define CP_WAIT2()  asm volatile("cp.async.wait_group 2;" ::: "memory")
#define CP_WAIT1()  asm volatile("cp.async.wait_group 1;" ::: "memory")
#define CP_WAIT0()  asm volatile("cp.async.wait_group 0;" ::: "memory")

// ===========================================================================
// Merged prep kernel: x -> fp16 hi/lo A-frags; W_kqv/W_proj -> fp16 B-frags
// ===========================================================================
__global__ __launch_bounds__(256)
void prep_all(const float* __restrict__ x, const float* __restrict__ Wk,
              const float* __restrict__ Wp)
{
    int blk = blockIdx.x;
    if (blk < 2048) {
        int slot = blk * 256 + threadIdx.x;
        int frag = slot >> 5, la = slot & 31;
        int row = ((frag >> 6) << 4) + (la >> 2);
        int k   = ((frag & 63) << 4) + ((la & 3) << 1);
        const float* p = x + (size_t)row * 1024 + k;
        float2 x0 = *(const float2*)p;
        float2 x1 = *(const float2*)(p + 8 * 1024);
        float2 x2 = *(const float2*)(p + 8);
        float2 x3 = *(const float2*)(p + 8 * 1024 + 8);
        uint4 h, l;
        hsplit2(x0, h.x, l.x);
        hsplit2(x1, h.y, l.y);
        hsplit2(x2, h.z, l.z);
        hsplit2(x3, h.w, l.w);
        g_xAh[slot] = h;
        g_xAl[slot] = l;
    } else {
        const float* src;
        uint2* hi;
        int slot;
        if (blk < 5120) {
            slot = (blk - 2048) * 256 + threadIdx.x;
            src = Wk; hi = g_WkBh;
        } else {
            slot = (blk - 5120) * 256 + threadIdx.x;
            src = Wp; hi = g_WpBh;
        }
        int frag = slot >> 5, la = slot & 31;
        int n = ((frag >> 6) << 3) + (la >> 2);
        int k = ((frag & 63) << 4) + ((la & 3) << 1);
        const float* p = src + (size_t)n * 1024 + k;
        float2 x0 = *(const float2*)p;
        float2 x1 = *(const float2*)(p + 8);
        uint2 h;
        h.x = packh2(x0.x, x0.y);
        h.y = packh2(x1.x, x1.y);
        hi[slot] = h;
    }
}

// ===========================================================================
// GEMM via fp16 mma.sync: A hi/lo x B single = 2 MMAs. Warp tile 64x64,
// 4 warps (2x2), 2 CTAs/SM. Stage 24KB: Ah[8K] Al[8K] Bh[8K]. 3 stages.
// ===========================================================================
#define GSTAGE 24576
#define GSMEM  (3 * GSTAGE)

__global__ __launch_bounds__(128, 2)
void gemm_hf(const uint4* __restrict__ Ah, const uint4* __restrict__ Al,
             const uint2* __restrict__ Bh,
             const float* __restrict__ bias, float* __restrict__ Cout,
             int N, int mode)
{
    extern __shared__ char smem[];
    const uint32_t sb = smem_u32(smem);
    const int tid = threadIdx.x;
    const int la  = tid & 31;
    const int wrp = tid >> 5;   // 0..3
    const int wm  = wrp >> 1;   // 0..1
    const int wn  = wrp & 1;    // 0..1
    const int r16b = blockIdx.y * 8;
    const int n8b  = blockIdx.x * 16;

    float acc[4][8][4];
#pragma unroll
    for (int i = 0; i < 4; i++)
#pragma unroll
        for (int j = 0; j < 8; j++)
#pragma unroll
            for (int r = 0; r < 4; r++) acc[i][j][r] = 0.f;

    auto issue = [&](int stage, int kc) {
        uint32_t base = sb + stage * GSTAGE;
#pragma unroll
        for (int rep = 0; rep < 4; rep++) {
            int u = rep * 128 + tid;           // 0..511
            int f = u >> 5, ln = u & 31;
            int ga = ((r16b + (f >> 1)) << 6) + (kc << 1) + (f & 1);
            CP16(base + f * 512 + ln * 16,        Ah + (size_t)ga * 32 + ln);
            CP16(base + 8192 + f * 512 + ln * 16, Al + (size_t)ga * 32 + ln);
        }
#pragma unroll
        for (int rep = 0; rep < 4; rep++) {
            int u = rep * 128 + tid;           // 0..511
            int f = u >> 4, j = u & 15;
            int gb = ((n8b + (f >> 1)) << 6) + (kc << 1) + (f & 1);
            CP16(base + 16384 + f * 256 + j * 16,
                 (const uint4*)Bh + (size_t)gb * 16 + j);
        }
        CP_COMMIT();
    };

    auto compute = [&](int stage) {
        char* base = smem + stage * GSTAGE;
#pragma unroll
        for (int kf = 0; kf < 2; kf++) {
            uint4 ah[4], al[4];
#pragma unroll
            for (int i = 0; i < 4; i++) {
                int foff = ((wm * 4 + i) * 2 + kf) * 512 + la * 16;
                ah[i] = *(const uint4*)(base + foff);
                al[i] = *(const uint4*)(base + 8192 + foff);
            }
#pragma unroll
            for (int jg = 0; jg < 2; jg++) {
                uint2 bh[4];
#pragma unroll
                for (int jj = 0; jj < 4; jj++) {
                    int boff = ((wn * 8 + jg * 4 + jj) * 2 + kf) * 256 + la * 8;
                    bh[jj] = *(const uint2*)(base + 16384 + boff);
                }
#pragma unroll
                for (int i = 0; i < 4; i++)
#pragma unroll
                    for (int jj = 0; jj < 4; jj++)
                        mma16816h(acc[i][jg * 4 + jj], ah[i], bh[jj]);
#pragma unroll
                for (int i = 0; i < 4; i++)
#pragma unroll
                    for (int jj = 0; jj < 4; jj++)
                        mma16816h(acc[i][jg * 4 + jj], al[i], bh[jj]);
            }
        }
    };

    issue(0, 0);
    issue(1, 1);

    for (int kc = 0; kc < 32; kc++) {
        if (kc + 2 < 32) {
            issue((kc + 2) % 3, kc + 2);
            CP_WAIT2();
        } else if (kc + 1 < 32) {
            CP_WAIT1();
        } else {
            CP_WAIT0();
        }
        __syncthreads();
        compute(kc % 3);
        __syncthreads();
    }

    const int brow = blockIdx.y * 128;
    const int bcol = blockIdx.x * 128;

    if (mode == 0) {
        // plain fp32 epilogue (+bias)
#pragma unroll
        for (int j = 0; j < 8; j++) {
            int c0 = bcol + wn * 64 + j * 8 + (la & 3) * 2;
            float bx = 0.f, by = 0.f;
            if (bias) { bx = bias[c0]; by = bias[c0 + 1]; }
#pragma unroll
            for (int i = 0; i < 4; i++) {
                int r0 = brow + wm * 64 + i * 16 + (la >> 2);
                float2 o0, o1;
                o0.x = acc[i][j][0] + bx; o0.y = acc[i][j][1] + by;
                o1.x = acc[i][j][2] + bx; o1.y = acc[i][j][3] + by;
                *(float2*)&Cout[(size_t)r0 * N + c0]       = o0;
                *(float2*)&Cout[(size_t)(r0 + 8) * N + c0] = o1;
            }
        }
    } else {
        // fused kqv epilogue. cols [0,1024)=k, [1024,2048)=q, [2048,3072)=v
        int role = bcol >> 10;
        if (role == 2) {
            // V: stage acc fp32 to smem, transpose, write fp16 V B-frag planes.
            float* VS = (float*)smem;   // [128][132] floats
#pragma unroll
            for (int j = 0; j < 8; j++) {
                int c0 = wn * 64 + j * 8 + (la & 3) * 2;
#pragma unroll
                for (int i = 0; i < 4; i++) {
                    int r0 = wm * 64 + i * 16 + (la >> 2);
                    VS[r0 * 132 + c0]           = acc[i][j][0];
                    VS[r0 * 132 + c0 + 1]       = acc[i][j][1];
                    VS[(r0 + 8) * 132 + c0]     = acc[i][j][2];
                    VS[(r0 + 8) * 132 + c0 + 1] = acc[i][j][3];
                }
            }
            __syncthreads();
            int b     = brow >> 11;
            int trow  = brow & 2047;
            int hbase = (bcol - 2048) >> 6;
#pragma unroll
            for (int it = 0; it < 32; it++) {
                int f   = it * 4 + wrp;          // 0..127 local frag
                int kf2 = f & 3;
                int nf  = (f >> 2) & 7;
                int ktl = (f >> 5) & 1;
                int hh  = f >> 6;
                int dl  = hh * 64 + nf * 8 + (la >> 2);
                int kl  = ktl * 64 + kf2 * 16 + (la & 3) * 2;
                float v00 = VS[kl * 132 + dl];
                float v01 = VS[(kl + 1) * 132 + dl];
                float v10 = VS[(kl + 8) * 132 + dl];
                float v11 = VS[(kl + 9) * 132 + dl];
                uint2 vh, vl;
                hsplit2(make_float2(v00, v01), vh.x, vl.x);
                hsplit2(make_float2(v10, v11), vh.y, vl.y);
                int BH = b * 16 + hbase + hh;
                int kt = (trow >> 6) + ktl;
                size_t slot = (size_t)(BH * 32 + kt) * 1024 + (nf * 4 + kf2) * 32 + la;
                g_VBh[slot] = vh;
                g_VBl[slot] = vl;
            }
        } else {
#pragma unroll
            for (int t = 0; t < 4; t++) {
                int gcol = (bcol & 1023) + wn * 64 + t * 16;
                int h  = gcol >> 6;
                int kf = (gcol >> 4) & 3;
#pragma unroll
                for (int i = 0; i < 4; i++) {
                    int grow = brow + wm * 64 + i * 16;
                    int b = grow >> 11, trow = grow & 2047;
                    int BH = b * 16 + h;
                    const float* a0 = acc[i][2 * t];
                    const float* a1 = acc[i][2 * t + 1];
                    if (role == 1) {
                        // Q A-frag: fp16 hi/lo, scale QSCALE
                        size_t slot = ((((size_t)BH * 128) + (trow >> 4)) * 4 + kf) * 32 + la;
                        uint4 ah4, al4;
                        hsplit2(make_float2(a0[0] * QSCALE, a0[1] * QSCALE), ah4.x, al4.x);
                        hsplit2(make_float2(a0[2] * QSCALE, a0[3] * QSCALE), ah4.y, al4.y);
                        hsplit2(make_float2(a1[0] * QSCALE, a1[1] * QSCALE), ah4.z, al4.z);
                        hsplit2(make_float2(a1[2] * QSCALE, a1[3] * QSCALE), ah4.w, al4.w);
                        g_QAh[slot] = ah4;
                        g_QAl[slot] = al4;
                    } else {
                        // K B-frags: single fp16
                        int kt = trow >> 6;
                        size_t fb = ((size_t)BH * 32 + kt) * 8;
                        size_t s0 = ((fb + 2 * i)     * 4 + kf) * 32 + la;
                        size_t s1 = ((fb + 2 * i + 1) * 4 + kf) * 32 + la;
                        uint2 h0, h1;
                        h0.x = packh2(a0[0], a0[1]);
                        h0.y = packh2(a1[0], a1[1]);
                        h1.x = packh2(a0[2], a0[3]);
                        h1.y = packh2(a1[2], a1[3]);
                        g_KBh[s0] = h0;
                        g_KBh[s1] = h1;
                    }
                }
            }
        }
    }
}

// ===========================================================================
// Flash attention (round-16: all fp16 paths). Only change: epilogue writes
// fp16 hi/lo A-frag planes for gemm2.
// Stage (24KB): KH [0,8K) | VH [8K,16K) | VL [16K,24K). 2 stages + Q 32KB.
// ===========================================================================
#define ASTAGE   24576
#define AQH_OFF  49152
#define AQL_OFF  65536
#define ATTN_SMEM 81920

__global__ __launch_bounds__(256, 2)
void attn_mma5()
{
    const int qt = 15 - blockIdx.x;   // heavy CTAs first
    const int h  = blockIdx.y;
    const int b  = blockIdx.z;
    const int BH = b * 16 + h;

    extern __shared__ char smem[];
    const uint32_t sb = smem_u32(smem);

    const int tid = threadIdx.x;
    const int la  = tid & 31;
    const int w   = tid >> 5;
    const int r_in  = la >> 2;
    const int cpair = (la & 3) * 2;
    const int qbase = qt * 128;
    const int row0  = qbase + w * 16 + r_in;
    const int row1  = row0 + 8;

    // --- issue Q fragments (one cp.async group, stays resident) ---
    {
        size_t qb = ((size_t)BH * 128 + qt * 8) * 128;   // uint4 units
#pragma unroll
        for (int rep = 0; rep < 4; rep++) {
            int u = rep * 256 + tid;                      // 0..1023
            CP16(sb + AQH_OFF + u * 16, g_QAh + qb + u);
            CP16(sb + AQL_OFF + u * 16, g_QAl + qb + u);
        }
        CP_COMMIT();
    }

    auto issue_tile = [&](int stage, int kt) {
        uint32_t base = sb + stage * ASTAGE;
        size_t t = ((size_t)BH * 32 + kt) * 512;
#pragma unroll
        for (int rep = 0; rep < 2; rep++) {
            int u = rep * 256 + tid;   // 0..511
            CP16(base + u * 16,         (const uint4*)g_KBh + t + u);
            CP16(base + 8192 + u * 16,  (const uint4*)g_VBh + t + u);
            CP16(base + 16384 + u * 16, (const uint4*)g_VBl + t + u);
        }
        CP_COMMIT();
    };

    float o[8][4];
#pragma unroll
    for (int nf = 0; nf < 8; nf++)
#pragma unroll
        for (int r = 0; r < 4; r++) o[nf][r] = 0.f;
    float m0 = -1e30f, m1 = -1e30f, l0 = 0.f, l1 = 0.f;

    const int ntiles = 2 * qt + 2;
    issue_tile(0, 0);

    for (int kt = 0; kt < ntiles; kt++) {
        if (kt + 1 < ntiles) {
            issue_tile((kt + 1) & 1, kt + 1);
            CP_WAIT1();
        } else {
            CP_WAIT0();
        }
        __syncthreads();

        char* stg = smem + (kt & 1) * ASTAGE;
        const int kbase = kt * 64;

        if (kbase <= qbase + w * 16 + 15) {
            // --- S = Q K^T  (fp16: Qh pass + Ql pass) ---
            float sfr[8][4];
#pragma unroll
            for (int nf = 0; nf < 8; nf++)
#pragma unroll
                for (int r = 0; r < 4; r++) sfr[nf][r] = 0.f;

#pragma unroll
            for (int kf = 0; kf < 4; kf++) {
                int qoff = ((w * 4 + kf) << 9) + (la << 4);
                uint4 qh = *(const uint4*)(smem + AQH_OFF + qoff);
                uint4 ql = *(const uint4*)(smem + AQL_OFF + qoff);
#pragma unroll
                for (int nf = 0; nf < 8; nf++) {
                    uint2 kh = *(const uint2*)(stg + ((nf * 4 + kf) << 8) + (la << 3));
                    mma16816h(sfr[nf], qh, kh);
                }
#pragma unroll
                for (int nf = 0; nf < 8; nf++) {
                    uint2 kh = *(const uint2*)(stg + ((nf * 4 + kf) << 8) + (la << 3));
                    mma16816h(sfr[nf], ql, kh);
                }
            }

            // --- causal mask (near-diagonal tiles only) ---
            if (kbase + 63 > qbase + w * 16) {
#pragma unroll
                for (int nf = 0; nf < 8; nf++) {
                    int c = kbase + nf * 8 + cpair;
                    if (c     > row0) sfr[nf][0] = -1e30f;
                    if (c + 1 > row0) sfr[nf][1] = -1e30f;
                    if (c     > row1) sfr[nf][2] = -1e30f;
                    if (c + 1 > row1) sfr[nf][3] = -1e30f;
                }
            }

            // --- online softmax (exp2 domain) ---
            float mx0 = -1e30f, mx1 = -1e30f;
#pragma unroll
            for (int nf = 0; nf < 8; nf++) {
                mx0 = fmaxf(mx0, fmaxf(sfr[nf][0], sfr[nf][1]));
                mx1 = fmaxf(mx1, fmaxf(sfr[nf][2], sfr[nf][3]));
            }
            mx0 = fmaxf(mx0, __shfl_xor_sync(0xffffffffu, mx0, 1));
            mx0 = fmaxf(mx0, __shfl_xor_sync(0xffffffffu, mx0, 2));
            mx1 = fmaxf(mx1, __shfl_xor_sync(0xffffffffu, mx1, 1));
            mx1 = fmaxf(mx1, __shfl_xor_sync(0xffffffffu, mx1, 2));

            float mn0 = fmaxf(m0, mx0), mn1 = fmaxf(m1, mx1);
            float a0 = ex2(m0 - mn0), a1 = ex2(m1 - mn1);
            float s0 = 0.f, s1 = 0.f;
#pragma unroll
            for (int nf = 0; nf < 8; nf++) {
                sfr[nf][0] = ex2(sfr[nf][0] - mn0);
                sfr[nf][1] = ex2(sfr[nf][1] - mn0);
                sfr[nf][2] = ex2(sfr[nf][2] - mn1);
                sfr[nf][3] = ex2(sfr[nf][3] - mn1);
                s0 += sfr[nf][0] + sfr[nf][1];
                s1 += sfr[nf][2] + sfr[nf][3];
            }
            s0 += __shfl_xor_sync(0xffffffffu, s0, 1);
            s0 += __shfl_xor_sync(0xffffffffu, s0, 2);
            s1 += __shfl_xor_sync(0xffffffffu, s1, 1);
            s1 += __shfl_xor_sync(0xffffffffu, s1, 2);

            l0 = l0 * a0 + s0;  l1 = l1 * a1 + s1;
            m0 = mn0;           m1 = mn1;
#pragma unroll
            for (int nf = 0; nf < 8; nf++) {
                o[nf][0] *= a0; o[nf][1] *= a0;
                o[nf][2] *= a1; o[nf][3] *= a1;
            }

            // --- O += P V  (P fp16, V fp16 hi/lo: 2 MMAs) ---
#pragma unroll
            for (int kf2 = 0; kf2 < 4; kf2++) {
                uint4 Ph;
                Ph.x = packh2(sfr[2 * kf2][0],     sfr[2 * kf2][1]);
                Ph.y = packh2(sfr[2 * kf2][2],     sfr[2 * kf2][3]);
                Ph.z = packh2(sfr[2 * kf2 + 1][0], sfr[2 * kf2 + 1][1]);
                Ph.w = packh2(sfr[2 * kf2 + 1][2], sfr[2 * kf2 + 1][3]);
#pragma unroll
                for (int nf = 0; nf < 8; nf++) {
                    uint2 vh = *(const uint2*)(stg + 8192 + ((nf * 4 + kf2) << 8) + (la << 3));
                    mma16816h(o[nf], Ph, vh);
                }
#pragma unroll
                for (int nf = 0; nf < 8; nf++) {
                    uint2 vl = *(const uint2*)(stg + 16384 + ((nf * 4 + kf2) << 8) + (la << 3));
                    mma16816h(o[nf], Ph, vl);
                }
            }
        }
        __syncthreads();
    }

    // --- epilogue: write gemm2 A-frag planes (fp16 hi/lo) ---
    float i0 = 1.f / l0, i1 = 1.f / l1;
    const int r16 = b * 128 + qt * 8 + w;
#pragma unroll
    for (int nf = 0; nf < 8; nf += 2) {
        int kfg = h * 4 + (nf >> 1);
        size_t slot = ((size_t)r16 * 64 + kfg) * 32 + la;
        uint4 ah4, al4;
        hsplit2(make_float2(o[nf][0] * i0,     o[nf][1] * i0),     ah4.x, al4.x);
        hsplit2(make_float2(o[nf][2] * i1,     o[nf][3] * i1),     ah4.y, al4.y);
        hsplit2(make_float2(o[nf + 1][0] * i0, o[nf + 1][1] * i0), ah4.z, al4.z);
        hsplit2(make_float2(o[nf + 1][2] * i1, o[nf + 1][3] * i1), ah4.w, al4.w);
        g_atAh[slot] = ah4;
        g_atAl[slot] = al4;
    }
}

// ---------------------------------------------------------------------------
// Launch
// ---------------------------------------------------------------------------
extern "C" void kernel_launch(void* const* d_in, const int* in_sizes, int n_in,
                              void* d_out, int out_size)
{
    const float* x = nullptr, *Wkqv = nullptr, *Wproj = nullptr, *bproj = nullptr;
    for (int i = 0; i < n_in; i++) {
        int sz = in_sizes[i];
        if      (sz == TB * TT * NE)      x     = (const float*)d_in[i];
        else if (sz == 3 * NE * NE)       Wkqv  = (const float*)d_in[i];
        else if (sz == NE * NE)           Wproj = (const float*)d_in[i];
        else if (sz == NE)                bproj = (const float*)d_in[i];
    }
    float* out = (float*)d_out;

    uint4 *xAh, *xAl, *atAh, *atAl;
    uint2 *WkBh, *WpBh;
    cudaGetSymbolAddress((void**)&xAh,  g_xAh);
    cudaGetSymbolAddress((void**)&xAl,  g_xAl);
    cudaGetSymbolAddress((void**)&atAh, g_atAh);
    cudaGetSymbolAddress((void**)&atAl, g_atAl);
    cudaGetSymbolAddress((void**)&WkBh, g_WkBh);
    cudaGetSymbolAddress((void**)&WpBh, g_WpBh);

    cudaFuncSetAttribute(gemm_hf,
                         cudaFuncAttributeMaxDynamicSharedMemorySize, GSMEM);
    cudaFuncSetAttribute(attn_mma5,
                         cudaFuncAttributeMaxDynamicSharedMemorySize, ATTN_SMEM);

    // Prep inputs (single launch)
    prep_all<<<6144, 256>>>(x, Wkqv, Wproj);

    // 1) KQV projection, fused epilogue -> Q/K/V fp16 frag planes
    {
        dim3 grid(C3 / 128, 32);
        gemm_hf<<<grid, 128, GSMEM>>>(xAh, xAl, WkBh, nullptr, out, NE, 1);
    }

    // 2) Causal flash attention -> g_atA planes
    {
        dim3 grid(TT / 128, NH, TB);
        attn_mma5<<<grid, 256, ATTN_SMEM>>>();
    }

    // 3) Output projection + bias
    {
        dim3 grid(NE / 128, 32);
        gemm_hf<<<grid, 128, GSMEM>>>(atAh, atAl, WpBh, bproj, out, NE, 0);
    }
}